// round 8
// baseline (speedup 1.0000x reference)
#include <cuda_runtime.h>
#include <cuda_bf16.h>
#include <math.h>
#include <stdint.h>

// Problem constants
#define BATCH 512
#define NTOK 85
#define DIM 512
#define HEADS 8
#define HD 64
#define M_ROWS (BATCH * NTOK)          // 43520
#define FFN 2048
#define QKVN 1536

// Weight layout offsets (quantized [N,K] int8, per layer, element==byte)
#define OFF_QKV 0
#define OFF_PROJ (QKVN * DIM)
#define OFF_FC1 (OFF_PROJ + DIM * DIM)
#define OFF_FC2 (OFF_FC1 + DIM * FFN)
#define LOFF (OFF_FC2 + FFN * DIM)     // 3145728
// Scale-row offsets within a layer (total 4608 N-rows per layer)
#define SOFF_QKV 0
#define SOFF_PROJ 1536
#define SOFF_FC1 2048
#define SOFF_FC2 4096
#define SROWS 4608

// Scratch (device globals; no allocation allowed)
static __device__ float g_x[M_ROWS * DIM];
static __device__ float g_qkv[M_ROWS * QKVN];
static __device__ float g_attn[M_ROWS * DIM];
static __device__ float g_fc1f[M_ROWS * FFN];
static __device__ __align__(16) int8_t g_qa1_512[M_ROWS * DIM];
static __device__ __align__(16) int8_t g_qa2_512[M_ROWS * DIM];
static __device__ __align__(16) int8_t g_qa1_2048[M_ROWS * FFN];
static __device__ __align__(16) int8_t g_qa2_2048[M_ROWS * FFN];
static __device__ __align__(16) int8_t g_wq1[6 * LOFF];
static __device__ __align__(16) int8_t g_wq2[6 * LOFF];
static __device__ float g_sA512[M_ROWS];
static __device__ float g_sA2048[M_ROWS];
static __device__ float g_sW[6 * SROWS];
static __device__ float g_sWinv[6 * SROWS];

// ---------------------------------------------------------------------------
__device__ __forceinline__ uint32_t smem_u32(const void* p) {
    uint32_t a;
    asm("{ .reg .u64 t; cvta.to.shared.u64 t, %1; cvt.u32.u64 %0, t; }" : "=r"(a) : "l"(p));
    return a;
}
__device__ __forceinline__ void cp16(uint32_t dst, const void* src) {
    asm volatile("cp.async.cg.shared.global [%0], [%1], 16;" :: "r"(dst), "l"(src));
}
__device__ __forceinline__ void ldmatrix_x4(uint32_t* r, uint32_t addr) {
    asm volatile("ldmatrix.sync.aligned.m8n8.x4.shared.b16 {%0,%1,%2,%3}, [%4];"
        : "=r"(r[0]), "=r"(r[1]), "=r"(r[2]), "=r"(r[3]) : "r"(addr));
}
__device__ __forceinline__ void mma_s8(int* d, const uint32_t* a, const uint32_t* b) {
    asm volatile(
        "mma.sync.aligned.m16n8k32.row.col.s32.s8.s8.s32 "
        "{%0,%1,%2,%3}, {%4,%5,%6,%7}, {%8,%9}, {%0,%1,%2,%3};"
        : "+r"(d[0]), "+r"(d[1]), "+r"(d[2]), "+r"(d[3])
        : "r"(a[0]), "r"(a[1]), "r"(a[2]), "r"(a[3]), "r"(b[0]), "r"(b[1]));
}

// Warp reductions
__device__ __forceinline__ float wred_sum(float v) {
    #pragma unroll
    for (int o = 16; o; o >>= 1) v += __shfl_xor_sync(0xFFFFFFFFu, v, o);
    return v;
}
__device__ __forceinline__ float wred_max(float v) {
    #pragma unroll
    for (int o = 16; o; o >>= 1) v = fmaxf(v, __shfl_xor_sync(0xFFFFFFFFu, v, o));
    return v;
}

// Quantize 4 floats -> packed int8 hi (u1) + lo (u2). a = s*(q1 + q2/128)
__device__ __forceinline__ void quant4pack(float4 v, float inv, uint32_t& u1, uint32_t& u2) {
    float q0 = v.x * inv, q1 = v.y * inv, q2 = v.z * inv, q3 = v.w * inv;
    int h0 = __float2int_rn(q0), h1 = __float2int_rn(q1);
    int h2 = __float2int_rn(q2), h3 = __float2int_rn(q3);
    int l0 = __float2int_rn((q0 - (float)h0) * 128.f);
    int l1 = __float2int_rn((q1 - (float)h1) * 128.f);
    int l2 = __float2int_rn((q2 - (float)h2) * 128.f);
    int l3 = __float2int_rn((q3 - (float)h3) * 128.f);
    u1 = (h0 & 0xFF) | ((h1 & 0xFF) << 8) | ((h2 & 0xFF) << 16) | ((h3 & 0xFF) << 24);
    u2 = (l0 & 0xFF) | ((l1 & 0xFF) << 8) | ((l2 & 0xFF) << 16) | ((l3 & 0xFF) << 24);
}

// ---------------------------------------------------------------------------
// Weight scale: per output row n, max |W[:,n]| over K. Coalesced over n.
__global__ void wmax_kernel(const float* __restrict__ W, float* __restrict__ sW,
                            float* __restrict__ sWinv, int K, int N) {
    int n = blockIdx.x * 256 + threadIdx.x;
    if (n >= N) return;
    float mx = 1e-30f;
    for (int k = 0; k < K; k++) mx = fmaxf(mx, fabsf(W[(size_t)k * N + n]));
    sW[n] = mx * (1.f / 127.f);
    sWinv[n] = 127.f / mx;
}

// Weight prep: W[K,N] fp32 -> q1/q2[N,K] int8 (transpose + quantize)
__global__ void prep_wq(const float* __restrict__ W, const float* __restrict__ sWinv,
                        int8_t* __restrict__ q1, int8_t* __restrict__ q2, int K, int N) {
    __shared__ float t[32][33];
    int n0 = blockIdx.x * 32, k0 = blockIdx.y * 32;
    int tx = threadIdx.x, ty = threadIdx.y;
    #pragma unroll
    for (int i = 0; i < 32; i += 8)
        t[ty + i][tx] = W[(size_t)(k0 + ty + i) * N + n0 + tx];
    __syncthreads();
    #pragma unroll
    for (int i = 0; i < 32; i += 8) {
        int n = n0 + ty + i, k = k0 + tx;
        float q = t[tx][ty + i] * sWinv[n];
        int h = __float2int_rn(q);
        int l = __float2int_rn((q - (float)h) * 128.f);
        q1[(size_t)n * K + k] = (int8_t)h;
        q2[(size_t)n * K + k] = (int8_t)l;
    }
}

// ---------------------------------------------------------------------------
// LayerNorm: one warp per row of 512. OUT=0: fp32 y. OUT=1: int8 quant.
template <int OUT>
__global__ void ln_kernel(const float* __restrict__ x, const float* __restrict__ w,
                          const float* __restrict__ b, float* __restrict__ y,
                          int8_t* __restrict__ q1, int8_t* __restrict__ q2,
                          float* __restrict__ sA) {
    int row = blockIdx.x * 8 + (threadIdx.x >> 5);
    int lane = threadIdx.x & 31;
    if (row >= M_ROWS) return;
    const float* xr = x + (size_t)row * DIM;
    float4 v[4];
    float s = 0.f, s2 = 0.f;
    #pragma unroll
    for (int i = 0; i < 4; i++) {
        v[i] = *(const float4*)(xr + i * 128 + lane * 4);
        s += v[i].x + v[i].y + v[i].z + v[i].w;
        s2 += v[i].x * v[i].x + v[i].y * v[i].y + v[i].z * v[i].z + v[i].w * v[i].w;
    }
    s = wred_sum(s); s2 = wred_sum(s2);
    float mu = s * (1.f / DIM);
    float var = s2 * (1.f / DIM) - mu * mu;
    float rstd = rsqrtf(var + 1e-5f);
    float4 ov[4];
    float mx = 0.f;
    #pragma unroll
    for (int i = 0; i < 4; i++) {
        int d = i * 128 + lane * 4;
        float4 wv = *(const float4*)(w + d);
        float4 bv = *(const float4*)(b + d);
        ov[i].x = (v[i].x - mu) * rstd * wv.x + bv.x;
        ov[i].y = (v[i].y - mu) * rstd * wv.y + bv.y;
        ov[i].z = (v[i].z - mu) * rstd * wv.z + bv.z;
        ov[i].w = (v[i].w - mu) * rstd * wv.w + bv.w;
        if (OUT == 1)
            mx = fmaxf(mx, fmaxf(fmaxf(fabsf(ov[i].x), fabsf(ov[i].y)),
                                 fmaxf(fabsf(ov[i].z), fabsf(ov[i].w))));
    }
    if (OUT == 0) {
        #pragma unroll
        for (int i = 0; i < 4; i++)
            *(float4*)(y + (size_t)row * DIM + i * 128 + lane * 4) = ov[i];
    } else {
        mx = wred_max(mx);
        mx = fmaxf(mx, 1e-20f);
        float inv = 127.f / mx;
        #pragma unroll
        for (int i = 0; i < 4; i++) {
            uint32_t u1, u2;
            quant4pack(ov[i], inv, u1, u2);
            size_t off = (size_t)row * DIM + i * 128 + lane * 4;
            *(uint32_t*)(q1 + off) = u1;
            *(uint32_t*)(q2 + off) = u2;
        }
        if (lane == 0) sA[row] = mx * (1.f / 127.f);
    }
}

// ---------------------------------------------------------------------------
// Row quantize fp32 [M, W] -> int8 q1/q2 + row scale. W = NF4*128.
template <int NF4>
__global__ void rowquant(const float* __restrict__ src,
                         int8_t* __restrict__ q1, int8_t* __restrict__ q2,
                         float* __restrict__ sA) {
    int row = blockIdx.x * 8 + (threadIdx.x >> 5);
    int lane = threadIdx.x & 31;
    if (row >= M_ROWS) return;
    const int W = NF4 * 128;
    const float* r = src + (size_t)row * W;
    float4 v[NF4];
    float mx = 0.f;
    #pragma unroll
    for (int i = 0; i < NF4; i++) {
        v[i] = *(const float4*)(r + i * 128 + lane * 4);
        mx = fmaxf(mx, fmaxf(fmaxf(fabsf(v[i].x), fabsf(v[i].y)),
                             fmaxf(fabsf(v[i].z), fabsf(v[i].w))));
    }
    mx = wred_max(mx);
    mx = fmaxf(mx, 1e-20f);
    float inv = 127.f / mx;
    #pragma unroll
    for (int i = 0; i < NF4; i++) {
        uint32_t u1, u2;
        quant4pack(v[i], inv, u1, u2);
        size_t off = (size_t)row * W + i * 128 + lane * 4;
        *(uint32_t*)(q1 + off) = u1;
        *(uint32_t*)(q2 + off) = u2;
    }
    if (lane == 0) sA[row] = mx * (1.f / 127.f);
}

// ---------------------------------------------------------------------------
// IMMA GEMM: out[M,N] = sA[m]*sW[n]*( q1A.q1B + (q1A.q2B + q2A.q1B)/128 ) + bias
// Tile 128x64, BK=64, 8 warps (grid 4x2, warp 32x32), double-buffered cp.async.
// EPI: 0 = bias, 1 = bias+GELU, 2 = bias+residual. Output fp32.
#define IPITCH 80
#define IA2 10240
#define IB1 20480
#define IB2 25600
#define IST 30720
#define IGSMEM (2 * IST)     // 61440

template <int EPI>
__global__ void __launch_bounds__(256, 2)
imma_gemm(const int8_t* __restrict__ qA1, const int8_t* __restrict__ qA2,
          const float* __restrict__ sA,
          const int8_t* __restrict__ qB1, const int8_t* __restrict__ qB2,
          const float* __restrict__ sW,
          const float* __restrict__ bias, const float* __restrict__ res,
          float* __restrict__ out, int M, int N, int K) {
    extern __shared__ char smem[];
    const uint32_t sb = smem_u32(smem);
    const int tid = threadIdx.x;
    const int wid = tid >> 5, lane = tid & 31;
    const int wm = wid >> 1, wn = wid & 1;    // warp grid 4 (M) x 2 (N)
    const int bm = blockIdx.y * 128, bn = blockIdx.x * 64;
    const int KT = K >> 6;

    const int8_t* pa1 = qA1 + (size_t)bm * K;
    const int8_t* pa2 = qA2 + (size_t)bm * K;
    const int8_t* pb1 = qB1 + (size_t)bn * K;
    const int8_t* pb2 = qB2 + (size_t)bn * K;

    auto load_stage = [&](int st, int k0) {
        const uint32_t sd = sb + st * IST;
        #pragma unroll
        for (int it = 0; it < 6; it++) {
            int c = tid + it * 256;
            if (c < 1024) {
                const int8_t* p = (c & 512) ? pa2 : pa1;
                int row = (c >> 2) & 127, seg = c & 3;
                cp16(sd + ((c & 512) ? IA2 : 0) + row * IPITCH + seg * 16,
                     p + (size_t)row * K + k0 + seg * 16);
            } else {
                int c2 = c - 1024;
                const int8_t* p = (c2 & 256) ? pb2 : pb1;
                int row = (c2 >> 2) & 63, seg = c2 & 3;
                cp16(sd + ((c2 & 256) ? IB2 : IB1) + row * IPITCH + seg * 16,
                     p + (size_t)row * K + k0 + seg * 16);
            }
        }
        asm volatile("cp.async.commit_group;" ::: "memory");
    };

    int accH[2][4][4] = {}, accM[2][4][4] = {};
    load_stage(0, 0);

    const int arow = lane & 15;
    const int abyte = (lane >> 4) << 4;
    const int brow = (lane & 7) + ((lane >> 4) << 3);
    const int bbyte = ((lane >> 3) & 1) << 4;

    for (int kt = 0; kt < KT; kt++) {
        const int st = kt & 1;
        if (kt + 1 < KT) {
            load_stage(st ^ 1, (kt + 1) << 6);
            asm volatile("cp.async.wait_group 1;" ::: "memory");
        } else {
            asm volatile("cp.async.wait_group 0;" ::: "memory");
        }
        __syncthreads();
        const uint32_t sd = sb + st * IST;
        #pragma unroll
        for (int kk = 0; kk < 2; kk++) {
            uint32_t b1[4][2], b2[4][2];
            #pragma unroll
            for (int p = 0; p < 2; p++) {
                uint32_t off = (uint32_t)(wn * 32 + p * 16 + brow) * IPITCH + kk * 32 + bbyte;
                uint32_t t[4];
                ldmatrix_x4(t, sd + IB1 + off);
                b1[2 * p][0] = t[0]; b1[2 * p][1] = t[1];
                b1[2 * p + 1][0] = t[2]; b1[2 * p + 1][1] = t[3];
                ldmatrix_x4(t, sd + IB2 + off);
                b2[2 * p][0] = t[0]; b2[2 * p][1] = t[1];
                b2[2 * p + 1][0] = t[2]; b2[2 * p + 1][1] = t[3];
            }
            #pragma unroll
            for (int mt = 0; mt < 2; mt++) {
                uint32_t a1[4], a2[4];
                uint32_t off = (uint32_t)(wm * 32 + mt * 16 + arow) * IPITCH + kk * 32 + abyte;
                ldmatrix_x4(a1, sd + off);
                ldmatrix_x4(a2, sd + IA2 + off);
                #pragma unroll
                for (int nt = 0; nt < 4; nt++) {
                    mma_s8(accH[mt][nt], a1, b1[nt]);
                    mma_s8(accM[mt][nt], a1, b2[nt]);
                    mma_s8(accM[mt][nt], a2, b1[nt]);
                }
            }
        }
        __syncthreads();
    }

    // Epilogue: c0,c1 = row er cols ec,ec+1; c2,c3 = row er+8.
    const int er = lane >> 2, ec = (lane & 3) * 2;
    #pragma unroll
    for (int mt = 0; mt < 2; mt++) {
        #pragma unroll
        for (int nt = 0; nt < 4; nt++) {
            const int n = bn + wn * 32 + nt * 8 + ec;
            const float sw0 = sW[n], sw1 = sW[n + 1];
            const float2 bv = *(const float2*)&bias[n];
            #pragma unroll
            for (int half = 0; half < 2; half++) {
                const int m = bm + wm * 32 + mt * 16 + er + half * 8;
                const float sa = sA[m];
                float o0 = sa * sw0 * ((float)accH[mt][nt][half * 2 + 0]
                           + (float)accM[mt][nt][half * 2 + 0] * 0.0078125f) + bv.x;
                float o1 = sa * sw1 * ((float)accH[mt][nt][half * 2 + 1]
                           + (float)accM[mt][nt][half * 2 + 1] * 0.0078125f) + bv.y;
                if (EPI == 1) {
                    o0 = 0.5f * o0 * (1.f + erff(o0 * 0.70710678118654752f));
                    o1 = 0.5f * o1 * (1.f + erff(o1 * 0.70710678118654752f));
                }
                if (EPI == 2) {
                    float2 rv = *(const float2*)&res[(size_t)m * N + n];
                    o0 += rv.x; o1 += rv.y;
                }
                *(float2*)&out[(size_t)m * N + n] = make_float2(o0, o1);
            }
        }
    }
}

// ---------------------------------------------------------------------------
// RoPE (2D), in place on q,k slices of qkv
__global__ void rope_kernel(float* __restrict__ qkv, const float* __restrict__ coords) {
    int idx = blockIdx.x * blockDim.x + threadIdx.x;
    if (idx >= M_ROWS * HEADS * 16) return;
    int j = idx & 15;
    int h = (idx >> 4) & 7;
    int t = idx >> 7;
    int n = t % NTOK;
    if (n == 0) return;
    float cxd = coords[(n - 1) * 2 + 0];
    float cyd = coords[(n - 1) * 2 + 1];
    float freq = __expf((float)j * -0.14391156509757025f);
    float sx, cx, sy, cy;
    sincosf(cxd * freq * 6.283185307179586f, &sx, &cx);
    sincosf(cyd * freq * 6.283185307179586f, &sy, &cy);
    size_t base = (size_t)t * QKVN + h * HD + j;
    #pragma unroll
    for (int o = 0; o <= 512; o += 512) {
        float x0 = qkv[base + o + 0];
        float x1 = qkv[base + o + 16];
        float x2 = qkv[base + o + 32];
        float x3 = qkv[base + o + 48];
        qkv[base + o + 0]  = x0 * cx - x1 * sx;
        qkv[base + o + 16] = x0 * sx + x1 * cx;
        qkv[base + o + 32] = x2 * cy - x3 * sy;
        qkv[base + o + 48] = x2 * sy + x3 * cy;
    }
}

// ---------------------------------------------------------------------------
// Attention: one block per (b,h); fp32 out
__device__ __forceinline__ int tok_grp(int i) {
    return (i >= 21) ? 3 : (i >= 5) ? 2 : (i >= 1) ? 1 : 0;
}
#define KPAD 65
#define ATTN_SMEM ((NTOK * KPAD * 2 + 8 * 64 + 8 * 96) * 4)

__global__ void attn_kernel(const float* __restrict__ qkv, float* __restrict__ out) {
    extern __shared__ float sm[];
    float* Ks = sm;
    float* Vs = Ks + NTOK * KPAD;
    float* Qs = Vs + NTOK * KPAD;
    float* Ps = Qs + 8 * 64;
    const int b = blockIdx.x >> 3;
    const int h = blockIdx.x & 7;
    const int tid = threadIdx.x;
    const int warp = tid >> 5, lane = tid & 31;
    const int allow_tbl[4] = {9, 3, 5, 8};

    const size_t base = (size_t)b * NTOK * QKVN + h * HD;
    for (int i = tid; i < NTOK * HD; i += 256) {
        int n = i >> 6, d = i & 63;
        Ks[n * KPAD + d] = qkv[base + (size_t)n * QKVN + 512 + d];
        Vs[n * KPAD + d] = qkv[base + (size_t)n * QKVN + 1024 + d];
    }
    __syncthreads();

    for (int r = warp; r < NTOK; r += 8) {
        Qs[warp * 64 + lane]      = qkv[base + (size_t)r * QKVN + lane];
        Qs[warp * 64 + lane + 32] = qkv[base + (size_t)r * QKVN + lane + 32];
        __syncwarp();
        const int arow = allow_tbl[tok_grp(r)];
        float s[3];
        float mx = -1e30f;
        #pragma unroll
        for (int t = 0; t < 3; t++) {
            int k = lane + t * 32;
            float v = -1e30f;
            if (k < NTOK) {
                float acc = 0.f;
                #pragma unroll
                for (int d = 0; d < 64; d++) acc += Qs[warp * 64 + d] * Ks[k * KPAD + d];
                bool allow = (arow >> tok_grp(k)) & 1;
                v = allow ? acc * 0.125f : -1e30f;
            }
            s[t] = v;
            mx = fmaxf(mx, v);
        }
        mx = wred_max(mx);
        float sum = 0.f;
        #pragma unroll
        for (int t = 0; t < 3; t++) {
            int k = lane + t * 32;
            if (k < NTOK) {
                float p = __expf(s[t] - mx);
                sum += p;
                Ps[warp * 96 + k] = p;
            }
        }
        sum = wred_sum(sum);
        float inv = 1.f / sum;
        __syncwarp();
        #pragma unroll
        for (int t = 0; t < 2; t++) {
            int d = lane + t * 32;
            float o = 0.f;
            for (int k = 0; k < NTOK; k++) o += Ps[warp * 96 + k] * Vs[k * KPAD + d];
            out[((size_t)b * NTOK + r) * DIM + h * HD + d] = o * inv;
        }
        __syncwarp();
    }
}

// ---------------------------------------------------------------------------
extern "C" void kernel_launch(void* const* d_in, const int* in_sizes, int n_in,
                              void* d_out, int out_size) {
    const float* x      = (const float*)d_in[0];
    const float* coords = (const float*)d_in[1];
    const float* ln1_w  = (const float*)d_in[2];
    const float* ln1_b  = (const float*)d_in[3];
    const float* qkv_w  = (const float*)d_in[4];
    const float* qkv_b  = (const float*)d_in[5];
    const float* proj_w = (const float*)d_in[6];
    const float* proj_b = (const float*)d_in[7];
    const float* ln2_w  = (const float*)d_in[8];
    const float* ln2_b  = (const float*)d_in[9];
    const float* fc1_w  = (const float*)d_in[10];
    const float* fc1_b  = (const float*)d_in[11];
    const float* fc2_w  = (const float*)d_in[12];
    const float* fc2_b  = (const float*)d_in[13];
    const float* lnf_w  = (const float*)d_in[14];
    const float* lnf_b  = (const float*)d_in[15];
    float* out = (float*)d_out;

    float *gx, *gqkv, *gattn, *gfc1, *gsA512, *gsA2048, *gsW, *gsWinv;
    int8_t *qa1_512, *qa2_512, *qa1_2048, *qa2_2048, *wq1, *wq2;
    cudaGetSymbolAddress((void**)&gx, g_x);
    cudaGetSymbolAddress((void**)&gqkv, g_qkv);
    cudaGetSymbolAddress((void**)&gattn, g_attn);
    cudaGetSymbolAddress((void**)&gfc1, g_fc1f);
    cudaGetSymbolAddress((void**)&qa1_512, g_qa1_512);
    cudaGetSymbolAddress((void**)&qa2_512, g_qa2_512);
    cudaGetSymbolAddress((void**)&qa1_2048, g_qa1_2048);
    cudaGetSymbolAddress((void**)&qa2_2048, g_qa2_2048);
    cudaGetSymbolAddress((void**)&wq1, g_wq1);
    cudaGetSymbolAddress((void**)&wq2, g_wq2);
    cudaGetSymbolAddress((void**)&gsA512, g_sA512);
    cudaGetSymbolAddress((void**)&gsA2048, g_sA2048);
    cudaGetSymbolAddress((void**)&gsW, g_sW);
    cudaGetSymbolAddress((void**)&gsWinv, g_sWinv);

    static int attr_set = 0;
    if (!attr_set) {
        cudaFuncSetAttribute(attn_kernel, cudaFuncAttributeMaxDynamicSharedMemorySize, ATTN_SMEM);
        cudaFuncSetAttribute(imma_gemm<0>, cudaFuncAttributeMaxDynamicSharedMemorySize, IGSMEM);
        cudaFuncSetAttribute(imma_gemm<1>, cudaFuncAttributeMaxDynamicSharedMemorySize, IGSMEM);
        cudaFuncSetAttribute(imma_gemm<2>, cudaFuncAttributeMaxDynamicSharedMemorySize, IGSMEM);
        attr_set = 1;
    }

    // Weight prep: per-row scale, then quantizing transpose (once per launch)
    for (int l = 0; l < 6; l++) {
        float* sWl = gsW + l * SROWS;
        float* sWil = gsWinv + l * SROWS;
        wmax_kernel<<<(QKVN + 255) / 256, 256>>>(qkv_w + (size_t)l * DIM * QKVN,
                                                 sWl + SOFF_QKV, sWil + SOFF_QKV, DIM, QKVN);
        wmax_kernel<<<(DIM + 255) / 256, 256>>>(proj_w + (size_t)l * DIM * DIM,
                                                sWl + SOFF_PROJ, sWil + SOFF_PROJ, DIM, DIM);
        wmax_kernel<<<(FFN + 255) / 256, 256>>>(fc1_w + (size_t)l * DIM * FFN,
                                                sWl + SOFF_FC1, sWil + SOFF_FC1, DIM, FFN);
        wmax_kernel<<<(DIM + 255) / 256, 256>>>(fc2_w + (size_t)l * FFN * DIM,
                                                sWl + SOFF_FC2, sWil + SOFF_FC2, FFN, DIM);
        prep_wq<<<dim3(QKVN / 32, DIM / 32), dim3(32, 8)>>>(
            qkv_w + (size_t)l * DIM * QKVN, sWil + SOFF_QKV,
            wq1 + (size_t)l * LOFF + OFF_QKV, wq2 + (size_t)l * LOFF + OFF_QKV, DIM, QKVN);
        prep_wq<<<dim3(DIM / 32, DIM / 32), dim3(32, 8)>>>(
            proj_w + (size_t)l * DIM * DIM, sWil + SOFF_PROJ,
            wq1 + (size_t)l * LOFF + OFF_PROJ, wq2 + (size_t)l * LOFF + OFF_PROJ, DIM, DIM);
        prep_wq<<<dim3(FFN / 32, DIM / 32), dim3(32, 8)>>>(
            fc1_w + (size_t)l * DIM * FFN, sWil + SOFF_FC1,
            wq1 + (size_t)l * LOFF + OFF_FC1, wq2 + (size_t)l * LOFF + OFF_FC1, DIM, FFN);
        prep_wq<<<dim3(DIM / 32, FFN / 32), dim3(32, 8)>>>(
            fc2_w + (size_t)l * FFN * DIM, sWil + SOFF_FC2,
            wq1 + (size_t)l * LOFF + OFF_FC2, wq2 + (size_t)l * LOFF + OFF_FC2, FFN, DIM);
    }

    cudaMemcpyAsync(gx, x, (size_t)M_ROWS * DIM * sizeof(float), cudaMemcpyDeviceToDevice, 0);

    const int ln_grid = (M_ROWS + 7) / 8;
    const int rope_grid = (M_ROWS * HEADS * 16 + 255) / 256;

    for (int l = 0; l < 6; l++) {
        const int8_t* w1 = wq1 + (size_t)l * LOFF;
        const int8_t* w2 = wq2 + (size_t)l * LOFF;
        const float* sWl = gsW + l * SROWS;

        // LN1 -> int8
        ln_kernel<1><<<ln_grid, 256>>>(gx, ln1_w + l * DIM, ln1_b + l * DIM,
                                       nullptr, qa1_512, qa2_512, gsA512);
        // QKV GEMM -> fp32
        imma_gemm<0><<<dim3(QKVN / 64, M_ROWS / 128), 256, IGSMEM>>>(
            qa1_512, qa2_512, gsA512, w1 + OFF_QKV, w2 + OFF_QKV, sWl + SOFF_QKV,
            qkv_b + (size_t)l * QKVN, nullptr, gqkv, M_ROWS, QKVN, DIM);
        // RoPE
        rope_kernel<<<rope_grid, 256>>>(gqkv, coords);
        // Attention -> fp32
        attn_kernel<<<BATCH * HEADS, 256, ATTN_SMEM>>>(gqkv, gattn);
        // quantize attention output
        rowquant<4><<<ln_grid, 256>>>(gattn, qa1_512, qa2_512, gsA512);
        // proj GEMM + residual -> g_x
        imma_gemm<2><<<dim3(DIM / 64, M_ROWS / 128), 256, IGSMEM>>>(
            qa1_512, qa2_512, gsA512, w1 + OFF_PROJ, w2 + OFF_PROJ, sWl + SOFF_PROJ,
            proj_b + (size_t)l * DIM, gx, gx, M_ROWS, DIM, DIM);
        // LN2 -> int8
        ln_kernel<1><<<ln_grid, 256>>>(gx, ln2_w + l * DIM, ln2_b + l * DIM,
                                       nullptr, qa1_512, qa2_512, gsA512);
        // fc1 + GELU -> fp32
        imma_gemm<1><<<dim3(FFN / 64, M_ROWS / 128), 256, IGSMEM>>>(
            qa1_512, qa2_512, gsA512, w1 + OFF_FC1, w2 + OFF_FC1, sWl + SOFF_FC1,
            fc1_b + (size_t)l * FFN, nullptr, gfc1, M_ROWS, FFN, DIM);
        // quantize fc1 output
        rowquant<16><<<ln_grid, 256>>>(gfc1, qa1_2048, qa2_2048, gsA2048);
        // fc2 + residual -> g_x
        imma_gemm<2><<<dim3(DIM / 64, M_ROWS / 128), 256, IGSMEM>>>(
            qa1_2048, qa2_2048, gsA2048, w1 + OFF_FC2, w2 + OFF_FC2, sWl + SOFF_FC2,
            fc2_b + (size_t)l * DIM, gx, gx, M_ROWS, DIM, FFN);
    }
    // Final LN -> out (fp32)
    ln_kernel<0><<<ln_grid, 256>>>(gx, lnf_w, lnf_b, out, nullptr, nullptr, nullptr);
}

// round 9
// speedup vs baseline: 3.6301x; 3.6301x over previous
#include <cuda_runtime.h>
#include <cuda_bf16.h>
#include <math.h>
#include <stdint.h>

// Problem constants
#define BATCH 512
#define NTOK 85
#define DIM 512
#define HEADS 8
#define HD 64
#define M_ROWS (BATCH * NTOK)          // 43520
#define FFN 2048
#define QKVN 1536

// Weight layout offsets (transposed [N,K] bf16, per layer)
#define OFF_QKV 0
#define OFF_PROJ (QKVN * DIM)
#define OFF_FC1 (OFF_PROJ + DIM * DIM)
#define OFF_FC2 (OFF_FC1 + DIM * FFN)
#define LOFF (OFF_FC2 + FFN * DIM)     // 3145728

// Scratch (device globals; no allocation allowed)
static __device__ float g_x[M_ROWS * DIM];
static __device__ float g_qkv[M_ROWS * QKVN];
static __device__ __nv_bfloat16 g_a512hi[M_ROWS * DIM];
static __device__ __nv_bfloat16 g_a512lo[M_ROWS * DIM];
static __device__ __nv_bfloat16 g_a2048hi[M_ROWS * FFN];
static __device__ __nv_bfloat16 g_a2048lo[M_ROWS * FFN];
static __device__ __nv_bfloat16 g_whi[6 * LOFF];
static __device__ __nv_bfloat16 g_wlo[6 * LOFF];

// ---------------------------------------------------------------------------
__device__ __forceinline__ uint32_t smem_u32(const void* p) {
    uint32_t a;
    asm("{ .reg .u64 t; cvta.to.shared.u64 t, %1; cvt.u32.u64 %0, t; }" : "=r"(a) : "l"(p));
    return a;
}
__device__ __forceinline__ void cp16(uint32_t dst, const void* src) {
    asm volatile("cp.async.cg.shared.global [%0], [%1], 16;" :: "r"(dst), "l"(src));
}
__device__ __forceinline__ void ldmatrix_x4(uint32_t* r, uint32_t addr) {
    asm volatile("ldmatrix.sync.aligned.m8n8.x4.shared.b16 {%0,%1,%2,%3}, [%4];"
        : "=r"(r[0]), "=r"(r[1]), "=r"(r[2]), "=r"(r[3]) : "r"(addr));
}
__device__ __forceinline__ void mma_bf16(float* d, const uint32_t* a, const uint32_t* b) {
    asm volatile(
        "mma.sync.aligned.m16n8k16.row.col.f32.bf16.bf16.f32 "
        "{%0,%1,%2,%3}, {%4,%5,%6,%7}, {%8,%9}, {%0,%1,%2,%3};"
        : "+f"(d[0]), "+f"(d[1]), "+f"(d[2]), "+f"(d[3])
        : "r"(a[0]), "r"(a[1]), "r"(a[2]), "r"(a[3]), "r"(b[0]), "r"(b[1]));
}

// Warp reductions
__device__ __forceinline__ float wred_sum(float v) {
    #pragma unroll
    for (int o = 16; o; o >>= 1) v += __shfl_xor_sync(0xFFFFFFFFu, v, o);
    return v;
}
__device__ __forceinline__ float wred_max(float v) {
    #pragma unroll
    for (int o = 16; o; o >>= 1) v = fmaxf(v, __shfl_xor_sync(0xFFFFFFFFu, v, o));
    return v;
}
__device__ __forceinline__ void split_bf16(float v, __nv_bfloat16& h, __nv_bfloat16& l) {
    h = __float2bfloat16(v);
    l = __float2bfloat16(v - __bfloat162float(h));
}

// ---------------------------------------------------------------------------
// Weight prep: W[K,N] fp32 -> Whi/Wlo[N,K] bf16 (transpose + split)
__global__ void prep_w(const float* __restrict__ W, __nv_bfloat16* __restrict__ Whi,
                       __nv_bfloat16* __restrict__ Wlo, int K, int N) {
    __shared__ float t[32][33];
    int n0 = blockIdx.x * 32, k0 = blockIdx.y * 32;
    int tx = threadIdx.x, ty = threadIdx.y;
    #pragma unroll
    for (int i = 0; i < 32; i += 8)
        t[ty + i][tx] = W[(size_t)(k0 + ty + i) * N + n0 + tx];
    __syncthreads();
    #pragma unroll
    for (int i = 0; i < 32; i += 8) {
        float v = t[tx][ty + i];
        __nv_bfloat16 h, l;
        split_bf16(v, h, l);
        size_t o = (size_t)(n0 + ty + i) * K + k0 + tx;
        Whi[o] = h; Wlo[o] = l;
    }
}

// ---------------------------------------------------------------------------
// LayerNorm (float4): one warp per row of 512. OUT=0: fp32 y. OUT=1: bf16 hi/lo.
template <int OUT>
__global__ void ln_kernel(const float* __restrict__ x, const float* __restrict__ w,
                          const float* __restrict__ b, float* __restrict__ y,
                          __nv_bfloat16* __restrict__ yhi, __nv_bfloat16* __restrict__ ylo) {
    int row = blockIdx.x * 8 + (threadIdx.x >> 5);
    int lane = threadIdx.x & 31;
    if (row >= M_ROWS) return;
    const float* xr = x + (size_t)row * DIM;
    float4 v[4];
    float s = 0.f, s2 = 0.f;
    #pragma unroll
    for (int i = 0; i < 4; i++) {
        v[i] = *(const float4*)(xr + i * 128 + lane * 4);
        s += v[i].x + v[i].y + v[i].z + v[i].w;
        s2 += v[i].x * v[i].x + v[i].y * v[i].y + v[i].z * v[i].z + v[i].w * v[i].w;
    }
    s = wred_sum(s); s2 = wred_sum(s2);
    float mu = s * (1.f / DIM);
    float var = s2 * (1.f / DIM) - mu * mu;
    float rstd = rsqrtf(var + 1e-5f);
    #pragma unroll
    for (int i = 0; i < 4; i++) {
        int d = i * 128 + lane * 4;
        float4 wv = *(const float4*)(w + d);
        float4 bv = *(const float4*)(b + d);
        float o0 = (v[i].x - mu) * rstd * wv.x + bv.x;
        float o1 = (v[i].y - mu) * rstd * wv.y + bv.y;
        float o2 = (v[i].z - mu) * rstd * wv.z + bv.z;
        float o3 = (v[i].w - mu) * rstd * wv.w + bv.w;
        if (OUT == 0) {
            *(float4*)(y + (size_t)row * DIM + d) = make_float4(o0, o1, o2, o3);
        } else {
            __nv_bfloat16 h0, l0, h1, l1, h2, l2, h3, l3;
            split_bf16(o0, h0, l0); split_bf16(o1, h1, l1);
            split_bf16(o2, h2, l2); split_bf16(o3, h3, l3);
            __nv_bfloat162 hp0, hp1, lp0, lp1;
            hp0.x = h0; hp0.y = h1; hp1.x = h2; hp1.y = h3;
            lp0.x = l0; lp0.y = l1; lp1.x = l2; lp1.y = l3;
            size_t off = (size_t)row * DIM + d;
            *(__nv_bfloat162*)(yhi + off) = hp0;
            *(__nv_bfloat162*)(yhi + off + 2) = hp1;
            *(__nv_bfloat162*)(ylo + off) = lp0;
            *(__nv_bfloat162*)(ylo + off + 2) = lp1;
        }
    }
}

// ---------------------------------------------------------------------------
// mma.sync GEMM: C[M,N] = (Ahi+Alo)[M,K] @ (Bhi+Blo)[N,K]^T  (3-MMA compensated)
// BM=128, BN=128, BK=32. 256 threads = 8 warps; warp tile 64x32. 2 CTAs/SM.
#define PITCHB 80
#define ARRB 10240            // 128 * 80
#define STAGEB (4 * ARRB)     // 40960
#define GSMEMB (2 * STAGEB)   // 81920

template <int EPI>
__global__ void __launch_bounds__(256, 2)
mma_gemm(const __nv_bfloat16* __restrict__ Ahi, const __nv_bfloat16* __restrict__ Alo,
         const __nv_bfloat16* __restrict__ Bhi, const __nv_bfloat16* __restrict__ Blo,
         const float* __restrict__ bias, const float* __restrict__ res,
         float* __restrict__ Cf, __nv_bfloat16* __restrict__ Chi, __nv_bfloat16* __restrict__ Clo,
         int M, int N, int K) {
    extern __shared__ char smem[];
    const uint32_t sb = smem_u32(smem);
    const int tid = threadIdx.x;
    const int wid = tid >> 5, lane = tid & 31;
    const int wm = wid & 1, wn = wid >> 1;     // warp grid 2 (M) x 4 (N)
    const int bm = blockIdx.y * 128, bn = blockIdx.x * 128;
    const int KT = K >> 5;

    const __nv_bfloat16* gp[4] = {
        Ahi + (size_t)bm * K, Alo + (size_t)bm * K,
        Bhi + (size_t)bn * K, Blo + (size_t)bn * K };

    const int r0 = tid >> 2, s0 = (tid & 3);
    const int r1 = (tid + 256) >> 2, s1 = ((tid + 256) & 3);

    auto load_stage = [&](int st, int k0) {
        const uint32_t sd = sb + st * STAGEB;
        #pragma unroll
        for (int arr = 0; arr < 4; arr++) {
            cp16(sd + arr * ARRB + r0 * PITCHB + s0 * 16, gp[arr] + (size_t)r0 * K + k0 + s0 * 8);
            cp16(sd + arr * ARRB + r1 * PITCHB + s1 * 16, gp[arr] + (size_t)r1 * K + k0 + s1 * 8);
        }
        asm volatile("cp.async.commit_group;" ::: "memory");
    };

    float acc[4][4][4];
    #pragma unroll
    for (int i = 0; i < 4; i++)
        #pragma unroll
        for (int j = 0; j < 4; j++)
            #pragma unroll
            for (int f = 0; f < 4; f++) acc[i][j][f] = 0.f;

    load_stage(0, 0);

    const int arow = (lane & 15);
    const int acol = (lane >> 4) << 3;
    const int brow = (lane & 7) + ((lane >> 4) << 3);
    const int bcol = ((lane >> 3) & 1) << 3;

    for (int kt = 0; kt < KT; kt++) {
        const int st = kt & 1;
        if (kt + 1 < KT) {
            load_stage(st ^ 1, (kt + 1) << 5);
            asm volatile("cp.async.wait_group 1;" ::: "memory");
        } else {
            asm volatile("cp.async.wait_group 0;" ::: "memory");
        }
        __syncthreads();
        const uint32_t sd = sb + st * STAGEB;
        #pragma unroll
        for (int kk = 0; kk < 2; kk++) {
            uint32_t bh[4][2], bl[4][2];
            #pragma unroll
            for (int p = 0; p < 2; p++) {
                uint32_t off = (uint32_t)(wn * 32 + p * 16 + brow) * PITCHB + (bcol + kk * 16) * 2;
                uint32_t t[4];
                ldmatrix_x4(t, sd + 2 * ARRB + off);
                bh[2 * p][0] = t[0]; bh[2 * p][1] = t[1];
                bh[2 * p + 1][0] = t[2]; bh[2 * p + 1][1] = t[3];
                ldmatrix_x4(t, sd + 3 * ARRB + off);
                bl[2 * p][0] = t[0]; bl[2 * p][1] = t[1];
                bl[2 * p + 1][0] = t[2]; bl[2 * p + 1][1] = t[3];
            }
            #pragma unroll
            for (int mt = 0; mt < 4; mt++) {
                uint32_t ah[4], al[4];
                uint32_t off = (uint32_t)(wm * 64 + mt * 16 + arow) * PITCHB + (acol + kk * 16) * 2;
                ldmatrix_x4(ah, sd + 0 * ARRB + off);
                ldmatrix_x4(al, sd + 1 * ARRB + off);
                #pragma unroll
                for (int nt = 0; nt < 4; nt++) {
                    mma_bf16(acc[mt][nt], ah, bh[nt]);
                    mma_bf16(acc[mt][nt], ah, bl[nt]);
                    mma_bf16(acc[mt][nt], al, bh[nt]);
                }
            }
        }
        __syncthreads();
    }

    const int er = lane >> 2, ec = (lane & 3) * 2;
    #pragma unroll
    for (int mt = 0; mt < 4; mt++) {
        #pragma unroll
        for (int nt = 0; nt < 4; nt++) {
            const int n = bn + wn * 32 + nt * 8 + ec;
            const float2 bv = *(const float2*)&bias[n];
            #pragma unroll
            for (int half = 0; half < 2; half++) {
                const int m = bm + wm * 64 + mt * 16 + er + half * 8;
                float o0 = acc[mt][nt][half * 2 + 0] + bv.x;
                float o1 = acc[mt][nt][half * 2 + 1] + bv.y;
                if (EPI == 1) {
                    o0 = 0.5f * o0 * (1.f + erff(o0 * 0.70710678118654752f));
                    o1 = 0.5f * o1 * (1.f + erff(o1 * 0.70710678118654752f));
                    __nv_bfloat16 h0, l0, h1, l1;
                    split_bf16(o0, h0, l0);
                    split_bf16(o1, h1, l1);
                    __nv_bfloat162 hp, lp;
                    hp.x = h0; hp.y = h1; lp.x = l0; lp.y = l1;
                    *(__nv_bfloat162*)&Chi[(size_t)m * N + n] = hp;
                    *(__nv_bfloat162*)&Clo[(size_t)m * N + n] = lp;
                } else {
                    if (EPI == 2) {
                        float2 rv = *(const float2*)&res[(size_t)m * N + n];
                        o0 += rv.x; o1 += rv.y;
                    }
                    float2 o = make_float2(o0, o1);
                    *(float2*)&Cf[(size_t)m * N + n] = o;
                }
            }
        }
    }
}

// ---------------------------------------------------------------------------
// RoPE (2D), in place on q,k slices of qkv
__global__ void rope_kernel(float* __restrict__ qkv, const float* __restrict__ coords) {
    int idx = blockIdx.x * blockDim.x + threadIdx.x;
    if (idx >= M_ROWS * HEADS * 16) return;
    int j = idx & 15;
    int h = (idx >> 4) & 7;
    int t = idx >> 7;
    int n = t % NTOK;
    if (n == 0) return;
    float cxd = coords[(n - 1) * 2 + 0];
    float cyd = coords[(n - 1) * 2 + 1];
    float freq = __expf((float)j * -0.14391156509757025f);
    float sx, cx, sy, cy;
    sincosf(cxd * freq * 6.283185307179586f, &sx, &cx);
    sincosf(cyd * freq * 6.283185307179586f, &sy, &cy);
    size_t base = (size_t)t * QKVN + h * HD + j;
    #pragma unroll
    for (int o = 0; o <= 512; o += 512) {
        float x0 = qkv[base + o + 0];
        float x1 = qkv[base + o + 16];
        float x2 = qkv[base + o + 32];
        float x3 = qkv[base + o + 48];
        qkv[base + o + 0]  = x0 * cx - x1 * sx;
        qkv[base + o + 16] = x0 * sx + x1 * cx;
        qkv[base + o + 32] = x2 * cy - x3 * sy;
        qkv[base + o + 48] = x2 * sy + x3 * cy;
    }
}

// ---------------------------------------------------------------------------
// Attention (float4 paths): one block per (b,h); output bf16 hi/lo
__device__ __forceinline__ int tok_grp(int i) {
    return (i >= 21) ? 3 : (i >= 5) ? 2 : (i >= 1) ? 1 : 0;
}
#define KPAD 68
#define ATTN_SMEM ((NTOK * KPAD * 2 + 8 * 64 + 8 * 96) * 4)

__global__ void attn_kernel(const float* __restrict__ qkv,
                            __nv_bfloat16* __restrict__ ohi, __nv_bfloat16* __restrict__ olo) {
    extern __shared__ float sm[];
    float* Ks = sm;
    float* Vs = Ks + NTOK * KPAD;
    float* Qs = Vs + NTOK * KPAD;       // 8 warps * 64
    float* Ps = Qs + 8 * 64;            // 8 warps * 96
    const int b = blockIdx.x >> 3;
    const int h = blockIdx.x & 7;
    const int tid = threadIdx.x;
    const int warp = tid >> 5, lane = tid & 31;
    const int allow_tbl[4] = {9, 3, 5, 8};

    const size_t base = (size_t)b * NTOK * QKVN + h * HD;
    // Stage K,V with float4 (alignment: all offsets are multiples of 4 floats)
    for (int i = tid; i < NTOK * 16; i += 256) {
        int n = i >> 4, d4 = (i & 15) << 2;
        float4 kv = *(const float4*)(qkv + base + (size_t)n * QKVN + 512 + d4);
        float4 vv = *(const float4*)(qkv + base + (size_t)n * QKVN + 1024 + d4);
        *(float4*)&Ks[n * KPAD + d4] = kv;
        *(float4*)&Vs[n * KPAD + d4] = vv;
    }
    __syncthreads();

    for (int r = warp; r < NTOK; r += 8) {
        // Q row -> smem (float4)
        if (lane < 16)
            *(float4*)&Qs[warp * 64 + lane * 4] =
                *(const float4*)(qkv + base + (size_t)r * QKVN + lane * 4);
        __syncwarp();
        const int arow = allow_tbl[tok_grp(r)];
        float s[3];
        float mx = -1e30f;
        #pragma unroll
        for (int t = 0; t < 3; t++) {
            int k = lane + t * 32;
            float v = -1e30f;
            if (k < NTOK) {
                float acc = 0.f;
                #pragma unroll
                for (int d4 = 0; d4 < 16; d4++) {
                    float4 q = *(float4*)&Qs[warp * 64 + d4 * 4];
                    float4 kk = *(float4*)&Ks[k * KPAD + d4 * 4];
                    acc += q.x * kk.x + q.y * kk.y + q.z * kk.z + q.w * kk.w;
                }
                bool allow = (arow >> tok_grp(k)) & 1;
                v = allow ? acc * 0.125f : -1e30f;
            }
            s[t] = v;
            mx = fmaxf(mx, v);
        }
        mx = wred_max(mx);
        float sum = 0.f;
        #pragma unroll
        for (int t = 0; t < 3; t++) {
            int k = lane + t * 32;
            if (k < NTOK) {
                float p = __expf(s[t] - mx);
                sum += p;
                Ps[warp * 96 + k] = p;
            }
        }
        sum = wred_sum(sum);
        float inv = 1.f / sum;
        __syncwarp();
        #pragma unroll
        for (int t = 0; t < 2; t++) {
            int d = lane + t * 32;
            float o = 0.f;
            // AV: unroll k by 4 with float4 P broadcast (84 = 21*4, +1 tail)
            #pragma unroll 4
            for (int k4 = 0; k4 < 21; k4++) {
                float4 p4 = *(float4*)&Ps[warp * 96 + k4 * 4];
                o += p4.x * Vs[(k4 * 4 + 0) * KPAD + d];
                o += p4.y * Vs[(k4 * 4 + 1) * KPAD + d];
                o += p4.z * Vs[(k4 * 4 + 2) * KPAD + d];
                o += p4.w * Vs[(k4 * 4 + 3) * KPAD + d];
            }
            o += Ps[warp * 96 + 84] * Vs[84 * KPAD + d];
            o *= inv;
            __nv_bfloat16 hh, ll;
            split_bf16(o, hh, ll);
            size_t oidx = ((size_t)b * NTOK + r) * DIM + h * HD + d;
            ohi[oidx] = hh;
            olo[oidx] = ll;
        }
        __syncwarp();
    }
}

// ---------------------------------------------------------------------------
extern "C" void kernel_launch(void* const* d_in, const int* in_sizes, int n_in,
                              void* d_out, int out_size) {
    const float* x      = (const float*)d_in[0];
    const float* coords = (const float*)d_in[1];
    const float* ln1_w  = (const float*)d_in[2];
    const float* ln1_b  = (const float*)d_in[3];
    const float* qkv_w  = (const float*)d_in[4];
    const float* qkv_b  = (const float*)d_in[5];
    const float* proj_w = (const float*)d_in[6];
    const float* proj_b = (const float*)d_in[7];
    const float* ln2_w  = (const float*)d_in[8];
    const float* ln2_b  = (const float*)d_in[9];
    const float* fc1_w  = (const float*)d_in[10];
    const float* fc1_b  = (const float*)d_in[11];
    const float* fc2_w  = (const float*)d_in[12];
    const float* fc2_b  = (const float*)d_in[13];
    const float* lnf_w  = (const float*)d_in[14];
    const float* lnf_b  = (const float*)d_in[15];
    float* out = (float*)d_out;

    float *gx, *gqkv;
    __nv_bfloat16 *a5h, *a5l, *a2h, *a2l, *whi, *wlo;
    cudaGetSymbolAddress((void**)&gx, g_x);
    cudaGetSymbolAddress((void**)&gqkv, g_qkv);
    cudaGetSymbolAddress((void**)&a5h, g_a512hi);
    cudaGetSymbolAddress((void**)&a5l, g_a512lo);
    cudaGetSymbolAddress((void**)&a2h, g_a2048hi);
    cudaGetSymbolAddress((void**)&a2l, g_a2048lo);
    cudaGetSymbolAddress((void**)&whi, g_whi);
    cudaGetSymbolAddress((void**)&wlo, g_wlo);

    static int attr_set = 0;
    if (!attr_set) {
        cudaFuncSetAttribute(attn_kernel, cudaFuncAttributeMaxDynamicSharedMemorySize, ATTN_SMEM);
        cudaFuncSetAttribute(mma_gemm<0>, cudaFuncAttributeMaxDynamicSharedMemorySize, GSMEMB);
        cudaFuncSetAttribute(mma_gemm<1>, cudaFuncAttributeMaxDynamicSharedMemorySize, GSMEMB);
        cudaFuncSetAttribute(mma_gemm<2>, cudaFuncAttributeMaxDynamicSharedMemorySize, GSMEMB);
        attr_set = 1;
    }

    // Weight prep: transpose + bf16 hi/lo split
    for (int l = 0; l < 6; l++) {
        prep_w<<<dim3(QKVN / 32, DIM / 32), dim3(32, 8)>>>(
            qkv_w + (size_t)l * DIM * QKVN, whi + (size_t)l * LOFF + OFF_QKV,
            wlo + (size_t)l * LOFF + OFF_QKV, DIM, QKVN);
        prep_w<<<dim3(DIM / 32, DIM / 32), dim3(32, 8)>>>(
            proj_w + (size_t)l * DIM * DIM, whi + (size_t)l * LOFF + OFF_PROJ,
            wlo + (size_t)l * LOFF + OFF_PROJ, DIM, DIM);
        prep_w<<<dim3(FFN / 32, DIM / 32), dim3(32, 8)>>>(
            fc1_w + (size_t)l * DIM * FFN, whi + (size_t)l * LOFF + OFF_FC1,
            wlo + (size_t)l * LOFF + OFF_FC1, DIM, FFN);
        prep_w<<<dim3(DIM / 32, FFN / 32), dim3(32, 8)>>>(
            fc2_w + (size_t)l * FFN * DIM, whi + (size_t)l * LOFF + OFF_FC2,
            wlo + (size_t)l * LOFF + OFF_FC2, FFN, DIM);
    }

    cudaMemcpyAsync(gx, x, (size_t)M_ROWS * DIM * sizeof(float), cudaMemcpyDeviceToDevice, 0);

    const int ln_grid = (M_ROWS + 7) / 8;
    const int rope_grid = (M_ROWS * HEADS * 16 + 255) / 256;

    for (int l = 0; l < 6; l++) {
        const __nv_bfloat16* qkvT_h = whi + (size_t)l * LOFF + OFF_QKV;
        const __nv_bfloat16* qkvT_l = wlo + (size_t)l * LOFF + OFF_QKV;
        const __nv_bfloat16* projT_h = whi + (size_t)l * LOFF + OFF_PROJ;
        const __nv_bfloat16* projT_l = wlo + (size_t)l * LOFF + OFF_PROJ;
        const __nv_bfloat16* fc1T_h = whi + (size_t)l * LOFF + OFF_FC1;
        const __nv_bfloat16* fc1T_l = wlo + (size_t)l * LOFF + OFF_FC1;
        const __nv_bfloat16* fc2T_h = whi + (size_t)l * LOFF + OFF_FC2;
        const __nv_bfloat16* fc2T_l = wlo + (size_t)l * LOFF + OFF_FC2;

        // LN1 -> bf16 hi/lo
        ln_kernel<1><<<ln_grid, 256>>>(gx, ln1_w + l * DIM, ln1_b + l * DIM, nullptr, a5h, a5l);
        // QKV GEMM -> fp32 qkv
        mma_gemm<0><<<dim3(QKVN / 128, M_ROWS / 128), 256, GSMEMB>>>(
            a5h, a5l, qkvT_h, qkvT_l, qkv_b + (size_t)l * QKVN, nullptr,
            gqkv, nullptr, nullptr, M_ROWS, QKVN, DIM);
        // RoPE
        rope_kernel<<<rope_grid, 256>>>(gqkv, coords);
        // Attention -> bf16 hi/lo
        attn_kernel<<<BATCH * HEADS, 256, ATTN_SMEM>>>(gqkv, a5h, a5l);
        // proj GEMM + residual -> g_x
        mma_gemm<2><<<dim3(DIM / 128, M_ROWS / 128), 256, GSMEMB>>>(
            a5h, a5l, projT_h, projT_l, proj_b + (size_t)l * DIM, gx,
            gx, nullptr, nullptr, M_ROWS, DIM, DIM);
        // LN2 -> bf16 hi/lo
        ln_kernel<1><<<ln_grid, 256>>>(gx, ln2_w + l * DIM, ln2_b + l * DIM, nullptr, a5h, a5l);
        // fc1 + GELU -> bf16 hi/lo
        mma_gemm<1><<<dim3(FFN / 128, M_ROWS / 128), 256, GSMEMB>>>(
            a5h, a5l, fc1T_h, fc1T_l, fc1_b + (size_t)l * FFN, nullptr,
            nullptr, a2h, a2l, M_ROWS, FFN, DIM);
        // fc2 + residual -> g_x
        mma_gemm<2><<<dim3(DIM / 128, M_ROWS / 128), 256, GSMEMB>>>(
            a2h, a2l, fc2T_h, fc2T_l, fc2_b + (size_t)l * DIM, gx,
            gx, nullptr, nullptr, M_ROWS, DIM, FFN);
    }
    // Final LN -> out (fp32)
    ln_kernel<0><<<ln_grid, 256>>>(gx, lnf_w, lnf_b, out, nullptr, nullptr);
}

// round 10
// speedup vs baseline: 6.1320x; 1.6892x over previous
#include <cuda_runtime.h>
#include <cuda_fp16.h>
#include <math.h>
#include <stdint.h>

// Problem constants
#define BATCH 512
#define NTOK 85
#define DIM 512
#define HEADS 8
#define HD 64
#define M_ROWS (BATCH * NTOK)          // 43520
#define FFN 2048
#define QKVN 1536

// Weight layout offsets (transposed [N,K] fp16, per layer)
#define OFF_QKV 0
#define OFF_PROJ (QKVN * DIM)
#define OFF_FC1 (OFF_PROJ + DIM * DIM)
#define OFF_FC2 (OFF_FC1 + DIM * FFN)
#define LOFF (OFF_FC2 + FFN * DIM)     // 3145728

// Scratch (device globals; no allocation allowed)
static __device__ float g_x[M_ROWS * DIM];
static __device__ float g_qkv[M_ROWS * QKVN];
static __device__ __half g_a512[M_ROWS * DIM];
static __device__ __half g_a2048[M_ROWS * FFN];
static __device__ __half g_wh[6 * LOFF];

// ---------------------------------------------------------------------------
__device__ __forceinline__ uint32_t smem_u32(const void* p) {
    uint32_t a;
    asm("{ .reg .u64 t; cvta.to.shared.u64 t, %1; cvt.u32.u64 %0, t; }" : "=r"(a) : "l"(p));
    return a;
}
__device__ __forceinline__ void cp16(uint32_t dst, const void* src) {
    asm volatile("cp.async.cg.shared.global [%0], [%1], 16;" :: "r"(dst), "l"(src));
}
__device__ __forceinline__ void ldmatrix_x4(uint32_t* r, uint32_t addr) {
    asm volatile("ldmatrix.sync.aligned.m8n8.x4.shared.b16 {%0,%1,%2,%3}, [%4];"
        : "=r"(r[0]), "=r"(r[1]), "=r"(r[2]), "=r"(r[3]) : "r"(addr));
}
__device__ __forceinline__ void mma_f16(float* d, const uint32_t* a, const uint32_t* b) {
    asm volatile(
        "mma.sync.aligned.m16n8k16.row.col.f32.f16.f16.f32 "
        "{%0,%1,%2,%3}, {%4,%5,%6,%7}, {%8,%9}, {%0,%1,%2,%3};"
        : "+f"(d[0]), "+f"(d[1]), "+f"(d[2]), "+f"(d[3])
        : "r"(a[0]), "r"(a[1]), "r"(a[2]), "r"(a[3]), "r"(b[0]), "r"(b[1]));
}

// Warp reductions
__device__ __forceinline__ float wred_sum(float v) {
    #pragma unroll
    for (int o = 16; o; o >>= 1) v += __shfl_xor_sync(0xFFFFFFFFu, v, o);
    return v;
}
__device__ __forceinline__ float wred_max(float v) {
    #pragma unroll
    for (int o = 16; o; o >>= 1) v = fmaxf(v, __shfl_xor_sync(0xFFFFFFFFu, v, o));
    return v;
}

// ---------------------------------------------------------------------------
// Weight prep: W[K,N] fp32 -> Wh[N,K] fp16 (transpose + convert)
__global__ void prep_w(const float* __restrict__ W, __half* __restrict__ Wh, int K, int N) {
    __shared__ float t[32][33];
    int n0 = blockIdx.x * 32, k0 = blockIdx.y * 32;
    int tx = threadIdx.x, ty = threadIdx.y;
    #pragma unroll
    for (int i = 0; i < 32; i += 8)
        t[ty + i][tx] = W[(size_t)(k0 + ty + i) * N + n0 + tx];
    __syncthreads();
    #pragma unroll
    for (int i = 0; i < 32; i += 8) {
        size_t o = (size_t)(n0 + ty + i) * K + k0 + tx;
        Wh[o] = __float2half(t[tx][ty + i]);
    }
}

// ---------------------------------------------------------------------------
// LayerNorm (float4): one warp per row of 512. OUT=0: fp32 y. OUT=1: fp16 yh.
template <int OUT>
__global__ void ln_kernel(const float* __restrict__ x, const float* __restrict__ w,
                          const float* __restrict__ b, float* __restrict__ y,
                          __half* __restrict__ yh) {
    int row = blockIdx.x * 8 + (threadIdx.x >> 5);
    int lane = threadIdx.x & 31;
    if (row >= M_ROWS) return;
    const float* xr = x + (size_t)row * DIM;
    float4 v[4];
    float s = 0.f, s2 = 0.f;
    #pragma unroll
    for (int i = 0; i < 4; i++) {
        v[i] = *(const float4*)(xr + i * 128 + lane * 4);
        s += v[i].x + v[i].y + v[i].z + v[i].w;
        s2 += v[i].x * v[i].x + v[i].y * v[i].y + v[i].z * v[i].z + v[i].w * v[i].w;
    }
    s = wred_sum(s); s2 = wred_sum(s2);
    float mu = s * (1.f / DIM);
    float var = s2 * (1.f / DIM) - mu * mu;
    float rstd = rsqrtf(var + 1e-5f);
    #pragma unroll
    for (int i = 0; i < 4; i++) {
        int d = i * 128 + lane * 4;
        float4 wv = *(const float4*)(w + d);
        float4 bv = *(const float4*)(b + d);
        float o0 = (v[i].x - mu) * rstd * wv.x + bv.x;
        float o1 = (v[i].y - mu) * rstd * wv.y + bv.y;
        float o2 = (v[i].z - mu) * rstd * wv.z + bv.z;
        float o3 = (v[i].w - mu) * rstd * wv.w + bv.w;
        if (OUT == 0) {
            *(float4*)(y + (size_t)row * DIM + d) = make_float4(o0, o1, o2, o3);
        } else {
            __half2 p0, p1;
            p0.x = __float2half(o0); p0.y = __float2half(o1);
            p1.x = __float2half(o2); p1.y = __float2half(o3);
            size_t off = (size_t)row * DIM + d;
            *(__half2*)(yh + off) = p0;
            *(__half2*)(yh + off + 2) = p1;
        }
    }
}

// ---------------------------------------------------------------------------
// fp16 mma.sync GEMM: C[M,N] = A[M,K] @ B[N,K]^T (+bias, epilogue)
// BM=128, BN=128, BK=32. 256 threads = 8 warps; warp tile 64x32. 2 CTAs/SM.
#define PITCHB 80
#define ARRB 10240            // 128 * 80
#define STAGEB (2 * ARRB)     // 20480 (A + B)
#define GSMEMB (2 * STAGEB)   // 40960

template <int EPI>
__global__ void __launch_bounds__(256, 2)
mma_gemm(const __half* __restrict__ A, const __half* __restrict__ B,
         const float* __restrict__ bias, const float* __restrict__ res,
         float* __restrict__ Cf, __half* __restrict__ Ch,
         int M, int N, int K) {
    extern __shared__ char smem[];
    const uint32_t sb = smem_u32(smem);
    const int tid = threadIdx.x;
    const int wid = tid >> 5, lane = tid & 31;
    const int wm = wid & 1, wn = wid >> 1;     // warp grid 2 (M) x 4 (N)
    const int bm = blockIdx.y * 128, bn = blockIdx.x * 128;
    const int KT = K >> 5;

    const __half* gp[2] = { A + (size_t)bm * K, B + (size_t)bn * K };

    auto load_stage = [&](int st, int k0) {
        const uint32_t sd = sb + st * STAGEB;
        #pragma unroll
        for (int i = 0; i < 4; i++) {
            int c = tid + i * 256;          // 0..1023
            int arr = c >> 9;               // 0 = A, 1 = B
            int within = c & 511;
            int row = within >> 2, seg = within & 3;
            cp16(sd + arr * ARRB + row * PITCHB + seg * 16,
                 gp[arr] + (size_t)row * K + k0 + seg * 8);
        }
        asm volatile("cp.async.commit_group;" ::: "memory");
    };

    float acc[4][4][4];
    #pragma unroll
    for (int i = 0; i < 4; i++)
        #pragma unroll
        for (int j = 0; j < 4; j++)
            #pragma unroll
            for (int f = 0; f < 4; f++) acc[i][j][f] = 0.f;

    load_stage(0, 0);

    const int arow = (lane & 15);
    const int acol = (lane >> 4) << 3;
    const int brow = (lane & 7) + ((lane >> 4) << 3);
    const int bcol = ((lane >> 3) & 1) << 3;

    for (int kt = 0; kt < KT; kt++) {
        const int st = kt & 1;
        if (kt + 1 < KT) {
            load_stage(st ^ 1, (kt + 1) << 5);
            asm volatile("cp.async.wait_group 1;" ::: "memory");
        } else {
            asm volatile("cp.async.wait_group 0;" ::: "memory");
        }
        __syncthreads();
        const uint32_t sd = sb + st * STAGEB;
        #pragma unroll
        for (int kk = 0; kk < 2; kk++) {
            uint32_t bh[4][2];
            #pragma unroll
            for (int p = 0; p < 2; p++) {
                uint32_t off = (uint32_t)(wn * 32 + p * 16 + brow) * PITCHB + (bcol + kk * 16) * 2;
                uint32_t t[4];
                ldmatrix_x4(t, sd + ARRB + off);
                bh[2 * p][0] = t[0]; bh[2 * p][1] = t[1];
                bh[2 * p + 1][0] = t[2]; bh[2 * p + 1][1] = t[3];
            }
            #pragma unroll
            for (int mt = 0; mt < 4; mt++) {
                uint32_t ah[4];
                uint32_t off = (uint32_t)(wm * 64 + mt * 16 + arow) * PITCHB + (acol + kk * 16) * 2;
                ldmatrix_x4(ah, sd + off);
                #pragma unroll
                for (int nt = 0; nt < 4; nt++)
                    mma_f16(acc[mt][nt], ah, bh[nt]);
            }
        }
        __syncthreads();
    }

    const int er = lane >> 2, ec = (lane & 3) * 2;
    #pragma unroll
    for (int mt = 0; mt < 4; mt++) {
        #pragma unroll
        for (int nt = 0; nt < 4; nt++) {
            const int n = bn + wn * 32 + nt * 8 + ec;
            const float2 bv = *(const float2*)&bias[n];
            #pragma unroll
            for (int half = 0; half < 2; half++) {
                const int m = bm + wm * 64 + mt * 16 + er + half * 8;
                float o0 = acc[mt][nt][half * 2 + 0] + bv.x;
                float o1 = acc[mt][nt][half * 2 + 1] + bv.y;
                if (EPI == 1) {
                    o0 = 0.5f * o0 * (1.f + erff(o0 * 0.70710678118654752f));
                    o1 = 0.5f * o1 * (1.f + erff(o1 * 0.70710678118654752f));
                    __half2 hp;
                    hp.x = __float2half(o0); hp.y = __float2half(o1);
                    *(__half2*)&Ch[(size_t)m * N + n] = hp;
                } else {
                    if (EPI == 2) {
                        float2 rv = *(const float2*)&res[(size_t)m * N + n];
                        o0 += rv.x; o1 += rv.y;
                    }
                    *(float2*)&Cf[(size_t)m * N + n] = make_float2(o0, o1);
                }
            }
        }
    }
}

// ---------------------------------------------------------------------------
// RoPE (2D), in place on q,k slices of qkv
__global__ void rope_kernel(float* __restrict__ qkv, const float* __restrict__ coords) {
    int idx = blockIdx.x * blockDim.x + threadIdx.x;
    if (idx >= M_ROWS * HEADS * 16) return;
    int j = idx & 15;
    int h = (idx >> 4) & 7;
    int t = idx >> 7;
    int n = t % NTOK;
    if (n == 0) return;
    float cxd = coords[(n - 1) * 2 + 0];
    float cyd = coords[(n - 1) * 2 + 1];
    float freq = __expf((float)j * -0.14391156509757025f);
    float sx, cx, sy, cy;
    sincosf(cxd * freq * 6.283185307179586f, &sx, &cx);
    sincosf(cyd * freq * 6.283185307179586f, &sy, &cy);
    size_t base = (size_t)t * QKVN + h * HD + j;
    #pragma unroll
    for (int o = 0; o <= 512; o += 512) {
        float x0 = qkv[base + o + 0];
        float x1 = qkv[base + o + 16];
        float x2 = qkv[base + o + 32];
        float x3 = qkv[base + o + 48];
        qkv[base + o + 0]  = x0 * cx - x1 * sx;
        qkv[base + o + 16] = x0 * sx + x1 * cx;
        qkv[base + o + 32] = x2 * cy - x3 * sy;
        qkv[base + o + 48] = x2 * sy + x3 * cy;
    }
}

// ---------------------------------------------------------------------------
// Attention (float4 paths): one block per (b,h); output fp16
__device__ __forceinline__ int tok_grp(int i) {
    return (i >= 21) ? 3 : (i >= 5) ? 2 : (i >= 1) ? 1 : 0;
}
#define KPAD 68
#define ATTN_SMEM ((NTOK * KPAD * 2 + 8 * 64 + 8 * 96) * 4)

__global__ void attn_kernel(const float* __restrict__ qkv, __half* __restrict__ oh) {
    extern __shared__ float sm[];
    float* Ks = sm;
    float* Vs = Ks + NTOK * KPAD;
    float* Qs = Vs + NTOK * KPAD;       // 8 warps * 64
    float* Ps = Qs + 8 * 64;            // 8 warps * 96
    const int b = blockIdx.x >> 3;
    const int h = blockIdx.x & 7;
    const int tid = threadIdx.x;
    const int warp = tid >> 5, lane = tid & 31;
    const int allow_tbl[4] = {9, 3, 5, 8};

    const size_t base = (size_t)b * NTOK * QKVN + h * HD;
    for (int i = tid; i < NTOK * 16; i += 256) {
        int n = i >> 4, d4 = (i & 15) << 2;
        float4 kv = *(const float4*)(qkv + base + (size_t)n * QKVN + 512 + d4);
        float4 vv = *(const float4*)(qkv + base + (size_t)n * QKVN + 1024 + d4);
        *(float4*)&Ks[n * KPAD + d4] = kv;
        *(float4*)&Vs[n * KPAD + d4] = vv;
    }
    __syncthreads();

    for (int r = warp; r < NTOK; r += 8) {
        if (lane < 16)
            *(float4*)&Qs[warp * 64 + lane * 4] =
                *(const float4*)(qkv + base + (size_t)r * QKVN + lane * 4);
        __syncwarp();
        const int arow = allow_tbl[tok_grp(r)];
        float s[3];
        float mx = -1e30f;
        #pragma unroll
        for (int t = 0; t < 3; t++) {
            int k = lane + t * 32;
            float v = -1e30f;
            if (k < NTOK) {
                float acc = 0.f;
                #pragma unroll
                for (int d4 = 0; d4 < 16; d4++) {
                    float4 q = *(float4*)&Qs[warp * 64 + d4 * 4];
                    float4 kk = *(float4*)&Ks[k * KPAD + d4 * 4];
                    acc += q.x * kk.x + q.y * kk.y + q.z * kk.z + q.w * kk.w;
                }
                bool allow = (arow >> tok_grp(k)) & 1;
                v = allow ? acc * 0.125f : -1e30f;
            }
            s[t] = v;
            mx = fmaxf(mx, v);
        }
        mx = wred_max(mx);
        float sum = 0.f;
        #pragma unroll
        for (int t = 0; t < 3; t++) {
            int k = lane + t * 32;
            if (k < NTOK) {
                float p = __expf(s[t] - mx);
                sum += p;
                Ps[warp * 96 + k] = p;
            }
        }
        sum = wred_sum(sum);
        float inv = 1.f / sum;
        __syncwarp();
        #pragma unroll
        for (int t = 0; t < 2; t++) {
            int d = lane + t * 32;
            float o = 0.f;
            #pragma unroll 4
            for (int k4 = 0; k4 < 21; k4++) {
                float4 p4 = *(float4*)&Ps[warp * 96 + k4 * 4];
                o += p4.x * Vs[(k4 * 4 + 0) * KPAD + d];
                o += p4.y * Vs[(k4 * 4 + 1) * KPAD + d];
                o += p4.z * Vs[(k4 * 4 + 2) * KPAD + d];
                o += p4.w * Vs[(k4 * 4 + 3) * KPAD + d];
            }
            o += Ps[warp * 96 + 84] * Vs[84 * KPAD + d];
            o *= inv;
            oh[((size_t)b * NTOK + r) * DIM + h * HD + d] = __float2half(o);
        }
        __syncwarp();
    }
}

// ---------------------------------------------------------------------------
extern "C" void kernel_launch(void* const* d_in, const int* in_sizes, int n_in,
                              void* d_out, int out_size) {
    const float* x      = (const float*)d_in[0];
    const float* coords = (const float*)d_in[1];
    const float* ln1_w  = (const float*)d_in[2];
    const float* ln1_b  = (const float*)d_in[3];
    const float* qkv_w  = (const float*)d_in[4];
    const float* qkv_b  = (const float*)d_in[5];
    const float* proj_w = (const float*)d_in[6];
    const float* proj_b = (const float*)d_in[7];
    const float* ln2_w  = (const float*)d_in[8];
    const float* ln2_b  = (const float*)d_in[9];
    const float* fc1_w  = (const float*)d_in[10];
    const float* fc1_b  = (const float*)d_in[11];
    const float* fc2_w  = (const float*)d_in[12];
    const float* fc2_b  = (const float*)d_in[13];
    const float* lnf_w  = (const float*)d_in[14];
    const float* lnf_b  = (const float*)d_in[15];
    float* out = (float*)d_out;

    float *gx, *gqkv;
    __half *a5, *a2, *wh;
    cudaGetSymbolAddress((void**)&gx, g_x);
    cudaGetSymbolAddress((void**)&gqkv, g_qkv);
    cudaGetSymbolAddress((void**)&a5, g_a512);
    cudaGetSymbolAddress((void**)&a2, g_a2048);
    cudaGetSymbolAddress((void**)&wh, g_wh);

    static int attr_set = 0;
    if (!attr_set) {
        cudaFuncSetAttribute(attn_kernel, cudaFuncAttributeMaxDynamicSharedMemorySize, ATTN_SMEM);
        cudaFuncSetAttribute(mma_gemm<0>, cudaFuncAttributeMaxDynamicSharedMemorySize, GSMEMB);
        cudaFuncSetAttribute(mma_gemm<1>, cudaFuncAttributeMaxDynamicSharedMemorySize, GSMEMB);
        cudaFuncSetAttribute(mma_gemm<2>, cudaFuncAttributeMaxDynamicSharedMemorySize, GSMEMB);
        attr_set = 1;
    }

    // Weight prep: transpose + fp16 convert
    for (int l = 0; l < 6; l++) {
        prep_w<<<dim3(QKVN / 32, DIM / 32), dim3(32, 8)>>>(
            qkv_w + (size_t)l * DIM * QKVN, wh + (size_t)l * LOFF + OFF_QKV, DIM, QKVN);
        prep_w<<<dim3(DIM / 32, DIM / 32), dim3(32, 8)>>>(
            proj_w + (size_t)l * DIM * DIM, wh + (size_t)l * LOFF + OFF_PROJ, DIM, DIM);
        prep_w<<<dim3(FFN / 32, DIM / 32), dim3(32, 8)>>>(
            fc1_w + (size_t)l * DIM * FFN, wh + (size_t)l * LOFF + OFF_FC1, DIM, FFN);
        prep_w<<<dim3(DIM / 32, FFN / 32), dim3(32, 8)>>>(
            fc2_w + (size_t)l * FFN * DIM, wh + (size_t)l * LOFF + OFF_FC2, FFN, DIM);
    }

    cudaMemcpyAsync(gx, x, (size_t)M_ROWS * DIM * sizeof(float), cudaMemcpyDeviceToDevice, 0);

    const int ln_grid = (M_ROWS + 7) / 8;
    const int rope_grid = (M_ROWS * HEADS * 16 + 255) / 256;

    for (int l = 0; l < 6; l++) {
        const __half* qkvT = wh + (size_t)l * LOFF + OFF_QKV;
        const __half* projT = wh + (size_t)l * LOFF + OFF_PROJ;
        const __half* fc1T = wh + (size_t)l * LOFF + OFF_FC1;
        const __half* fc2T = wh + (size_t)l * LOFF + OFF_FC2;

        // LN1 -> fp16
        ln_kernel<1><<<ln_grid, 256>>>(gx, ln1_w + l * DIM, ln1_b + l * DIM, nullptr, a5);
        // QKV GEMM -> fp32 qkv
        mma_gemm<0><<<dim3(QKVN / 128, M_ROWS / 128), 256, GSMEMB>>>(
            a5, qkvT, qkv_b + (size_t)l * QKVN, nullptr,
            gqkv, nullptr, M_ROWS, QKVN, DIM);
        // RoPE
        rope_kernel<<<rope_grid, 256>>>(gqkv, coords);
        // Attention -> fp16
        attn_kernel<<<BATCH * HEADS, 256, ATTN_SMEM>>>(gqkv, a5);
        // proj GEMM + residual -> g_x
        mma_gemm<2><<<dim3(DIM / 128, M_ROWS / 128), 256, GSMEMB>>>(
            a5, projT, proj_b + (size_t)l * DIM, gx,
            gx, nullptr, M_ROWS, DIM, DIM);
        // LN2 -> fp16
        ln_kernel<1><<<ln_grid, 256>>>(gx, ln2_w + l * DIM, ln2_b + l * DIM, nullptr, a5);
        // fc1 + GELU -> fp16
        mma_gemm<1><<<dim3(FFN / 128, M_ROWS / 128), 256, GSMEMB>>>(
            a5, fc1T, fc1_b + (size_t)l * FFN, nullptr,
            nullptr, a2, M_ROWS, FFN, DIM);
        // fc2 + residual -> g_x
        mma_gemm<2><<<dim3(DIM / 128, M_ROWS / 128), 256, GSMEMB>>>(
            a2, fc2T, fc2_b + (size_t)l * DIM, gx,
            gx, nullptr, M_ROWS, DIM, FFN);
    }
    // Final LN -> out (fp32)
    ln_kernel<0><<<ln_grid, 256>>>(gx, lnf_w, lnf_b, out, nullptr);
}

// round 14
// speedup vs baseline: 6.4488x; 1.0517x over previous
#include <cuda_runtime.h>
#include <cuda_fp16.h>
#include <math.h>
#include <stdint.h>

// Problem constants
#define BATCH 512
#define NTOK 85
#define DIM 512
#define HEADS 8
#define HD 64
#define M_ROWS (BATCH * NTOK)          // 43520
#define FFN 2048
#define QKVN 1536

// Weight layout offsets (transposed [N,K] fp16, per layer)
#define OFF_QKV 0
#define OFF_PROJ (QKVN * DIM)
#define OFF_FC1 (OFF_PROJ + DIM * DIM)
#define OFF_FC2 (OFF_FC1 + DIM * FFN)
#define LOFF (OFF_FC2 + FFN * DIM)     // 3145728

// Scratch (device globals; no allocation allowed)
static __device__ float g_x[M_ROWS * DIM];
static __device__ float g_qkv[M_ROWS * QKVN];
static __device__ __half g_a512[M_ROWS * DIM];
static __device__ __half g_a2048[M_ROWS * FFN];
static __device__ __half g_wh[6 * LOFF];

// ---------------------------------------------------------------------------
__device__ __forceinline__ uint32_t smem_u32(const void* p) {
    uint32_t a;
    asm("{ .reg .u64 t; cvta.to.shared.u64 t, %1; cvt.u32.u64 %0, t; }" : "=r"(a) : "l"(p));
    return a;
}
__device__ __forceinline__ void cp16(uint32_t dst, const void* src) {
    asm volatile("cp.async.cg.shared.global [%0], [%1], 16;" :: "r"(dst), "l"(src));
}
__device__ __forceinline__ void ldmatrix_x4(uint32_t* r, uint32_t addr) {
    asm volatile("ldmatrix.sync.aligned.m8n8.x4.shared.b16 {%0,%1,%2,%3}, [%4];"
        : "=r"(r[0]), "=r"(r[1]), "=r"(r[2]), "=r"(r[3]) : "r"(addr));
}
__device__ __forceinline__ void mma_f16(float* d, const uint32_t* a, const uint32_t* b) {
    asm volatile(
        "mma.sync.aligned.m16n8k16.row.col.f32.f16.f16.f32 "
        "{%0,%1,%2,%3}, {%4,%5,%6,%7}, {%8,%9}, {%0,%1,%2,%3};"
        : "+f"(d[0]), "+f"(d[1]), "+f"(d[2]), "+f"(d[3])
        : "r"(a[0]), "r"(a[1]), "r"(a[2]), "r"(a[3]), "r"(b[0]), "r"(b[1]));
}

// Warp reductions
__device__ __forceinline__ float wred_sum(float v) {
    #pragma unroll
    for (int o = 16; o; o >>= 1) v += __shfl_xor_sync(0xFFFFFFFFu, v, o);
    return v;
}
__device__ __forceinline__ float wred_max(float v) {
    #pragma unroll
    for (int o = 16; o; o >>= 1) v = fmaxf(v, __shfl_xor_sync(0xFFFFFFFFu, v, o));
    return v;
}

// ---------------------------------------------------------------------------
// Weight prep: W[K,N] fp32 -> Wh[N,K] fp16 (transpose + convert)
__global__ void prep_w(const float* __restrict__ W, __half* __restrict__ Wh, int K, int N) {
    __shared__ float t[32][33];
    int n0 = blockIdx.x * 32, k0 = blockIdx.y * 32;
    int tx = threadIdx.x, ty = threadIdx.y;
    #pragma unroll
    for (int i = 0; i < 32; i += 8)
        t[ty + i][tx] = W[(size_t)(k0 + ty + i) * N + n0 + tx];
    __syncthreads();
    #pragma unroll
    for (int i = 0; i < 32; i += 8) {
        size_t o = (size_t)(n0 + ty + i) * K + k0 + tx;
        Wh[o] = __float2half(t[tx][ty + i]);
    }
}

// ---------------------------------------------------------------------------
// LayerNorm (float4): one warp per row of 512. OUT=0: fp32 y. OUT=1: fp16 yh.
template <int OUT>
__global__ void ln_kernel(const float* __restrict__ x, const float* __restrict__ w,
                          const float* __restrict__ b, float* __restrict__ y,
                          __half* __restrict__ yh) {
    int row = blockIdx.x * 8 + (threadIdx.x >> 5);
    int lane = threadIdx.x & 31;
    if (row >= M_ROWS) return;
    const float* xr = x + (size_t)row * DIM;
    float4 v[4];
    float s = 0.f, s2 = 0.f;
    #pragma unroll
    for (int i = 0; i < 4; i++) {
        v[i] = *(const float4*)(xr + i * 128 + lane * 4);
        s += v[i].x + v[i].y + v[i].z + v[i].w;
        s2 += v[i].x * v[i].x + v[i].y * v[i].y + v[i].z * v[i].z + v[i].w * v[i].w;
    }
    s = wred_sum(s); s2 = wred_sum(s2);
    float mu = s * (1.f / DIM);
    float var = s2 * (1.f / DIM) - mu * mu;
    float rstd = rsqrtf(var + 1e-5f);
    #pragma unroll
    for (int i = 0; i < 4; i++) {
        int d = i * 128 + lane * 4;
        float4 wv = *(const float4*)(w + d);
        float4 bv = *(const float4*)(b + d);
        float o0 = (v[i].x - mu) * rstd * wv.x + bv.x;
        float o1 = (v[i].y - mu) * rstd * wv.y + bv.y;
        float o2 = (v[i].z - mu) * rstd * wv.z + bv.z;
        float o3 = (v[i].w - mu) * rstd * wv.w + bv.w;
        if (OUT == 0) {
            *(float4*)(y + (size_t)row * DIM + d) = make_float4(o0, o1, o2, o3);
        } else {
            __half2 p0, p1;
            p0.x = __float2half(o0); p0.y = __float2half(o1);
            p1.x = __float2half(o2); p1.y = __float2half(o3);
            size_t off = (size_t)row * DIM + d;
            *(__half2*)(yh + off) = p0;
            *(__half2*)(yh + off + 2) = p1;
        }
    }
}

// ---------------------------------------------------------------------------
// fp16 mma.sync GEMM: C[M,N] = A[M,K] @ B[N,K]^T (+bias, epilogue)
// BM=128, BN=128, BK=32. 128 threads = 4 warps (2x2); warp tile 64x64. 2 CTAs/SM.
#define PITCHB 80
#define ARRB 10240            // 128 * 80
#define STAGEB (2 * ARRB)     // 20480 (A + B)
#define GSMEMB (2 * STAGEB)   // 40960

template <int EPI>
__global__ void __launch_bounds__(128, 2)
mma_gemm(const __half* __restrict__ A, const __half* __restrict__ B,
         const float* __restrict__ bias, const float* __restrict__ res,
         float* __restrict__ Cf, __half* __restrict__ Ch,
         int M, int N, int K) {
    extern __shared__ char smem[];
    const uint32_t sb = smem_u32(smem);
    const int tid = threadIdx.x;
    const int wid = tid >> 5, lane = tid & 31;
    const int wm = wid & 1, wn = wid >> 1;     // warp grid 2 (M) x 2 (N), tile 64x64
    const int bm = blockIdx.y * 128, bn = blockIdx.x * 128;
    const int KT = K >> 5;

    const __half* gp[2] = { A + (size_t)bm * K, B + (size_t)bn * K };

    auto load_stage = [&](int st, int k0) {
        const uint32_t sd = sb + st * STAGEB;
        #pragma unroll
        for (int i = 0; i < 8; i++) {
            int c = tid + i * 128;          // 0..1023
            int arr = c >> 9;               // 0 = A, 1 = B
            int within = c & 511;
            int row = within >> 2, seg = within & 3;
            cp16(sd + arr * ARRB + row * PITCHB + seg * 16,
                 gp[arr] + (size_t)row * K + k0 + seg * 8);
        }
        asm volatile("cp.async.commit_group;" ::: "memory");
    };

    float acc[4][8][4];
    #pragma unroll
    for (int i = 0; i < 4; i++)
        #pragma unroll
        for (int j = 0; j < 8; j++)
            #pragma unroll
            for (int f = 0; f < 4; f++) acc[i][j][f] = 0.f;

    load_stage(0, 0);

    const int arow = (lane & 15);
    const int acol = (lane >> 4) << 3;
    const int brow = (lane & 7) + ((lane >> 4) << 3);
    const int bcol = ((lane >> 3) & 1) << 3;

    for (int kt = 0; kt < KT; kt++) {
        const int st = kt & 1;
        if (kt + 1 < KT) {
            load_stage(st ^ 1, (kt + 1) << 5);
            asm volatile("cp.async.wait_group 1;" ::: "memory");
        } else {
            asm volatile("cp.async.wait_group 0;" ::: "memory");
        }
        __syncthreads();
        const uint32_t sd = sb + st * STAGEB;
        #pragma unroll
        for (int kk = 0; kk < 2; kk++) {
            uint32_t bh[8][2];
            #pragma unroll
            for (int p = 0; p < 4; p++) {
                uint32_t off = (uint32_t)(wn * 64 + p * 16 + brow) * PITCHB + (bcol + kk * 16) * 2;
                uint32_t t[4];
                ldmatrix_x4(t, sd + ARRB + off);
                bh[2 * p][0] = t[0]; bh[2 * p][1] = t[1];
                bh[2 * p + 1][0] = t[2]; bh[2 * p + 1][1] = t[3];
            }
            #pragma unroll
            for (int mt = 0; mt < 4; mt++) {
                uint32_t ah[4];
                uint32_t off = (uint32_t)(wm * 64 + mt * 16 + arow) * PITCHB + (acol + kk * 16) * 2;
                ldmatrix_x4(ah, sd + off);
                #pragma unroll
                for (int nt = 0; nt < 8; nt++)
                    mma_f16(acc[mt][nt], ah, bh[nt]);
            }
        }
        __syncthreads();
    }

    const int er = lane >> 2, ec = (lane & 3) * 2;
    #pragma unroll
    for (int mt = 0; mt < 4; mt++) {
        #pragma unroll
        for (int nt = 0; nt < 8; nt++) {
            const int n = bn + wn * 64 + nt * 8 + ec;
            const float2 bv = *(const float2*)&bias[n];
            #pragma unroll
            for (int half = 0; half < 2; half++) {
                const int m = bm + wm * 64 + mt * 16 + er + half * 8;
                float o0 = acc[mt][nt][half * 2 + 0] + bv.x;
                float o1 = acc[mt][nt][half * 2 + 1] + bv.y;
                if (EPI == 1) {
                    o0 = 0.5f * o0 * (1.f + erff(o0 * 0.70710678118654752f));
                    o1 = 0.5f * o1 * (1.f + erff(o1 * 0.70710678118654752f));
                    __half2 hp;
                    hp.x = __float2half(o0); hp.y = __float2half(o1);
                    *(__half2*)&Ch[(size_t)m * N + n] = hp;
                } else {
                    if (EPI == 2) {
                        float2 rv = *(const float2*)&res[(size_t)m * N + n];
                        o0 += rv.x; o1 += rv.y;
                    }
                    *(float2*)&Cf[(size_t)m * N + n] = make_float2(o0, o1);
                }
            }
        }
    }
}

// ---------------------------------------------------------------------------
// Attention with fused 2D RoPE: one block per (b,h); output fp16.
// qkv is UNROPED; K rotated in smem after staging, Q rotated on row load.
__device__ __forceinline__ int tok_grp(int i) {
    return (i >= 21) ? 3 : (i >= 5) ? 2 : (i >= 1) ? 1 : 0;
}
#define KPAD 68
#define ATTN_SMEM ((NTOK * KPAD * 2 + 8 * 64 + 8 * 96) * 4)
#define TWO_PI 6.283185307179586f
#define NLOG10_16 -0.14391156509757025f

__global__ void attn_kernel(const float* __restrict__ qkv,
                            const float* __restrict__ coords,
                            __half* __restrict__ oh) {
    extern __shared__ float sm[];
    float* Ks = sm;
    float* Vs = Ks + NTOK * KPAD;
    float* Qs = Vs + NTOK * KPAD;       // 8 warps * 64
    float* Ps = Qs + 8 * 64;            // 8 warps * 96
    const int b = blockIdx.x >> 3;
    const int h = blockIdx.x & 7;
    const int tid = threadIdx.x;
    const int warp = tid >> 5, lane = tid & 31;
    const int allow_tbl[4] = {9, 3, 5, 8};

    const size_t base = (size_t)b * NTOK * QKVN + h * HD;
    // Stage K,V (float4)
    for (int i = tid; i < NTOK * 16; i += 256) {
        int n = i >> 4, d4 = (i & 15) << 2;
        float4 kv = *(const float4*)(qkv + base + (size_t)n * QKVN + 512 + d4);
        float4 vv = *(const float4*)(qkv + base + (size_t)n * QKVN + 1024 + d4);
        *(float4*)&Ks[n * KPAD + d4] = kv;
        *(float4*)&Vs[n * KPAD + d4] = vv;
    }
    __syncthreads();
    // RoPE on K in smem: tokens 1..84, j 0..15
    for (int i = tid; i < NTOK * 16; i += 256) {
        int n = i >> 4, j = i & 15;
        if (n == 0) continue;
        float freq = __expf((float)j * NLOG10_16) * TWO_PI;
        float sx, cx, sy, cy;
        sincosf(coords[(n - 1) * 2 + 0] * freq, &sx, &cx);
        sincosf(coords[(n - 1) * 2 + 1] * freq, &sy, &cy);
        float* kr = Ks + n * KPAD + j;
        float x0 = kr[0], x1 = kr[16], x2 = kr[32], x3 = kr[48];
        kr[0]  = x0 * cx - x1 * sx;
        kr[16] = x0 * sx + x1 * cx;
        kr[32] = x2 * cy - x3 * sy;
        kr[48] = x2 * sy + x3 * cy;
    }
    __syncthreads();

    for (int r = warp; r < NTOK; r += 8) {
        if (lane < 16)
            *(float4*)&Qs[warp * 64 + lane * 4] =
                *(const float4*)(qkv + base + (size_t)r * QKVN + lane * 4);
        __syncwarp();
        // RoPE on Q row (lanes 0..15 each handle one j)
        if (r > 0 && lane < 16) {
            int j = lane;
            float freq = __expf((float)j * NLOG10_16) * TWO_PI;
            float sx, cx, sy, cy;
            sincosf(coords[(r - 1) * 2 + 0] * freq, &sx, &cx);
            sincosf(coords[(r - 1) * 2 + 1] * freq, &sy, &cy);
            float* qr = Qs + warp * 64 + j;
            float x0 = qr[0], x1 = qr[16], x2 = qr[32], x3 = qr[48];
            qr[0]  = x0 * cx - x1 * sx;
            qr[16] = x0 * sx + x1 * cx;
            qr[32] = x2 * cy - x3 * sy;
            qr[48] = x2 * sy + x3 * cy;
        }
        __syncwarp();
        const int arow = allow_tbl[tok_grp(r)];
        float s[3];
        float mx = -1e30f;
        #pragma unroll
        for (int t = 0; t < 3; t++) {
            int k = lane + t * 32;
            float v = -1e30f;
            if (k < NTOK) {
                float acc = 0.f;
                #pragma unroll
                for (int d4 = 0; d4 < 16; d4++) {
                    float4 q = *(float4*)&Qs[warp * 64 + d4 * 4];
                    float4 kk = *(float4*)&Ks[k * KPAD + d4 * 4];
                    acc += q.x * kk.x + q.y * kk.y + q.z * kk.z + q.w * kk.w;
                }
                bool allow = (arow >> tok_grp(k)) & 1;
                v = allow ? acc * 0.125f : -1e30f;
            }
            s[t] = v;
            mx = fmaxf(mx, v);
        }
        mx = wred_max(mx);
        float sum = 0.f;
        #pragma unroll
        for (int t = 0; t < 3; t++) {
            int k = lane + t * 32;
            if (k < NTOK) {
                float p = __expf(s[t] - mx);
                sum += p;
                Ps[warp * 96 + k] = p;
            }
        }
        sum = wred_sum(sum);
        float inv = 1.f / sum;
        __syncwarp();
        #pragma unroll
        for (int t = 0; t < 2; t++) {
            int d = lane + t * 32;
            float o = 0.f;
            #pragma unroll 4
            for (int k4 = 0; k4 < 21; k4++) {
                float4 p4 = *(float4*)&Ps[warp * 96 + k4 * 4];
                o += p4.x * Vs[(k4 * 4 + 0) * KPAD + d];
                o += p4.y * Vs[(k4 * 4 + 1) * KPAD + d];
                o += p4.z * Vs[(k4 * 4 + 2) * KPAD + d];
                o += p4.w * Vs[(k4 * 4 + 3) * KPAD + d];
            }
            o += Ps[warp * 96 + 84] * Vs[84 * KPAD + d];
            o *= inv;
            oh[((size_t)b * NTOK + r) * DIM + h * HD + d] = __float2half(o);
        }
        __syncwarp();
    }
}

// ---------------------------------------------------------------------------
extern "C" void kernel_launch(void* const* d_in, const int* in_sizes, int n_in,
                              void* d_out, int out_size) {
    const float* x      = (const float*)d_in[0];
    const float* coords = (const float*)d_in[1];
    const float* ln1_w  = (const float*)d_in[2];
    const float* ln1_b  = (const float*)d_in[3];
    const float* qkv_w  = (const float*)d_in[4];
    const float* qkv_b  = (const float*)d_in[5];
    const float* proj_w = (const float*)d_in[6];
    const float* proj_b = (const float*)d_in[7];
    const float* ln2_w  = (const float*)d_in[8];
    const float* ln2_b  = (const float*)d_in[9];
    const float* fc1_w  = (const float*)d_in[10];
    const float* fc1_b  = (const float*)d_in[11];
    const float* fc2_w  = (const float*)d_in[12];
    const float* fc2_b  = (const float*)d_in[13];
    const float* lnf_w  = (const float*)d_in[14];
    const float* lnf_b  = (const float*)d_in[15];
    float* out = (float*)d_out;

    float *gx, *gqkv;
    __half *a5, *a2, *wh;
    cudaGetSymbolAddress((void**)&gx, g_x);
    cudaGetSymbolAddress((void**)&gqkv, g_qkv);
    cudaGetSymbolAddress((void**)&a5, g_a512);
    cudaGetSymbolAddress((void**)&a2, g_a2048);
    cudaGetSymbolAddress((void**)&wh, g_wh);

    static int attr_set = 0;
    if (!attr_set) {
        cudaFuncSetAttribute(attn_kernel, cudaFuncAttributeMaxDynamicSharedMemorySize, ATTN_SMEM);
        cudaFuncSetAttribute(mma_gemm<0>, cudaFuncAttributeMaxDynamicSharedMemorySize, GSMEMB);
        cudaFuncSetAttribute(mma_gemm<1>, cudaFuncAttributeMaxDynamicSharedMemorySize, GSMEMB);
        cudaFuncSetAttribute(mma_gemm<2>, cudaFuncAttributeMaxDynamicSharedMemorySize, GSMEMB);
        attr_set = 1;
    }

    // Weight prep: transpose + fp16 convert
    for (int l = 0; l < 6; l++) {
        prep_w<<<dim3(QKVN / 32, DIM / 32), dim3(32, 8)>>>(
            qkv_w + (size_t)l * DIM * QKVN, wh + (size_t)l * LOFF + OFF_QKV, DIM, QKVN);
        prep_w<<<dim3(DIM / 32, DIM / 32), dim3(32, 8)>>>(
            proj_w + (size_t)l * DIM * DIM, wh + (size_t)l * LOFF + OFF_PROJ, DIM, DIM);
        prep_w<<<dim3(FFN / 32, DIM / 32), dim3(32, 8)>>>(
            fc1_w + (size_t)l * DIM * FFN, wh + (size_t)l * LOFF + OFF_FC1, DIM, FFN);
        prep_w<<<dim3(DIM / 32, FFN / 32), dim3(32, 8)>>>(
            fc2_w + (size_t)l * FFN * DIM, wh + (size_t)l * LOFF + OFF_FC2, FFN, DIM);
    }

    cudaMemcpyAsync(gx, x, (size_t)M_ROWS * DIM * sizeof(float), cudaMemcpyDeviceToDevice, 0);

    const int ln_grid = (M_ROWS + 7) / 8;

    for (int l = 0; l < 6; l++) {
        const __half* qkvT = wh + (size_t)l * LOFF + OFF_QKV;
        const __half* projT = wh + (size_t)l * LOFF + OFF_PROJ;
        const __half* fc1T = wh + (size_t)l * LOFF + OFF_FC1;
        const __half* fc2T = wh + (size_t)l * LOFF + OFF_FC2;

        // LN1 -> fp16
        ln_kernel<1><<<ln_grid, 256>>>(gx, ln1_w + l * DIM, ln1_b + l * DIM, nullptr, a5);
        // QKV GEMM -> fp32 qkv (unroped; rope fused into attention)
        mma_gemm<0><<<dim3(QKVN / 128, M_ROWS / 128), 128, GSMEMB>>>(
            a5, qkvT, qkv_b + (size_t)l * QKVN, nullptr,
            gqkv, nullptr, M_ROWS, QKVN, DIM);
        // Attention (fused RoPE) -> fp16
        attn_kernel<<<BATCH * HEADS, 256, ATTN_SMEM>>>(gqkv, coords, a5);
        // proj GEMM + residual -> g_x
        mma_gemm<2><<<dim3(DIM / 128, M_ROWS / 128), 128, GSMEMB>>>(
            a5, projT, proj_b + (size_t)l * DIM, gx,
            gx, nullptr, M_ROWS, DIM, DIM);
        // LN2 -> fp16
        ln_kernel<1><<<ln_grid, 256>>>(gx, ln2_w + l * DIM, ln2_b + l * DIM, nullptr, a5);
        // fc1 + GELU -> fp16
        mma_gemm<1><<<dim3(FFN / 128, M_ROWS / 128), 128, GSMEMB>>>(
            a5, fc1T, fc1_b + (size_t)l * FFN, nullptr,
            nullptr, a2, M_ROWS, FFN, DIM);
        // fc2 + residual -> g_x
        mma_gemm<2><<<dim3(DIM / 128, M_ROWS / 128), 128, GSMEMB>>>(
            a2, fc2T, fc2_b + (size_t)l * DIM, gx,
            gx, nullptr, M_ROWS, DIM, FFN);
    }
    // Final LN -> out (fp32)
    ln_kernel<0><<<ln_grid, 256>>>(gx, lnf_w, lnf_b, out, nullptr);
}

// round 17
// speedup vs baseline: 6.8080x; 1.0557x over previous
#include <cuda_runtime.h>
#include <cuda_fp16.h>
#include <math.h>
#include <stdint.h>

// Problem constants
#define BATCH 512
#define NTOK 85
#define DIM 512
#define HEADS 8
#define HD 64
#define M_ROWS (BATCH * NTOK)          // 43520
#define FFN 2048
#define QKVN 1536

// Weight layout offsets (transposed [N,K] fp16, per layer)
#define OFF_QKV 0
#define OFF_PROJ (QKVN * DIM)
#define OFF_FC1 (OFF_PROJ + DIM * DIM)
#define OFF_FC2 (OFF_FC1 + DIM * FFN)
#define LOFF (OFF_FC2 + FFN * DIM)     // 3145728

// Scratch (device globals; no allocation allowed)
static __device__ float g_x[M_ROWS * DIM];
static __device__ __half g_qkvh[M_ROWS * QKVN];
static __device__ __half g_a512[M_ROWS * DIM];
static __device__ __half g_a2048[M_ROWS * FFN];
static __device__ __half g_wh[6 * LOFF];

// ---------------------------------------------------------------------------
__device__ __forceinline__ uint32_t smem_u32(const void* p) {
    uint32_t a;
    asm("{ .reg .u64 t; cvta.to.shared.u64 t, %1; cvt.u32.u64 %0, t; }" : "=r"(a) : "l"(p));
    return a;
}
__device__ __forceinline__ void cp16(uint32_t dst, const void* src) {
    asm volatile("cp.async.cg.shared.global [%0], [%1], 16;" :: "r"(dst), "l"(src));
}
__device__ __forceinline__ void ldmatrix_x4(uint32_t* r, uint32_t addr) {
    asm volatile("ldmatrix.sync.aligned.m8n8.x4.shared.b16 {%0,%1,%2,%3}, [%4];"
        : "=r"(r[0]), "=r"(r[1]), "=r"(r[2]), "=r"(r[3]) : "r"(addr));
}
__device__ __forceinline__ void mma_f16(float* d, const uint32_t* a, const uint32_t* b) {
    asm volatile(
        "mma.sync.aligned.m16n8k16.row.col.f32.f16.f16.f32 "
        "{%0,%1,%2,%3}, {%4,%5,%6,%7}, {%8,%9}, {%0,%1,%2,%3};"
        : "+f"(d[0]), "+f"(d[1]), "+f"(d[2]), "+f"(d[3])
        : "r"(a[0]), "r"(a[1]), "r"(a[2]), "r"(a[3]), "r"(b[0]), "r"(b[1]));
}

// Warp reductions
__device__ __forceinline__ float wred_sum(float v) {
    #pragma unroll
    for (int o = 16; o; o >>= 1) v += __shfl_xor_sync(0xFFFFFFFFu, v, o);
    return v;
}
__device__ __forceinline__ float wred_max(float v) {
    #pragma unroll
    for (int o = 16; o; o >>= 1) v = fmaxf(v, __shfl_xor_sync(0xFFFFFFFFu, v, o));
    return v;
}
// Load 8 fp16 -> 8 fp32 into (32B-aligned) dst
__device__ __forceinline__ void ld8h_to_f(const __half* p, float* dst) {
    uint4 u = *(const uint4*)p;
    const __half2* hp = (const __half2*)&u;
    #pragma unroll
    for (int i = 0; i < 4; i++) {
        float2 f = __half22float2(hp[i]);
        dst[2 * i] = f.x; dst[2 * i + 1] = f.y;
    }
}

// ---------------------------------------------------------------------------
// Weight prep: W[K,N] fp32 -> Wh[N,K] fp16 (transpose + convert)
__global__ void prep_w(const float* __restrict__ W, __half* __restrict__ Wh, int K, int N) {
    __shared__ float t[32][33];
    int n0 = blockIdx.x * 32, k0 = blockIdx.y * 32;
    int tx = threadIdx.x, ty = threadIdx.y;
    #pragma unroll
    for (int i = 0; i < 32; i += 8)
        t[ty + i][tx] = W[(size_t)(k0 + ty + i) * N + n0 + tx];
    __syncthreads();
    #pragma unroll
    for (int i = 0; i < 32; i += 8) {
        size_t o = (size_t)(n0 + ty + i) * K + k0 + tx;
        Wh[o] = __float2half(t[tx][ty + i]);
    }
}

// ---------------------------------------------------------------------------
// LayerNorm (float4): one warp per row of 512. OUT=0: fp32 y. OUT=1: fp16 yh.
template <int OUT>
__global__ void ln_kernel(const float* __restrict__ x, const float* __restrict__ w,
                          const float* __restrict__ b, float* __restrict__ y,
                          __half* __restrict__ yh) {
    int row = blockIdx.x * 8 + (threadIdx.x >> 5);
    int lane = threadIdx.x & 31;
    if (row >= M_ROWS) return;
    const float* xr = x + (size_t)row * DIM;
    float4 v[4];
    float s = 0.f, s2 = 0.f;
    #pragma unroll
    for (int i = 0; i < 4; i++) {
        v[i] = *(const float4*)(xr + i * 128 + lane * 4);
        s += v[i].x + v[i].y + v[i].z + v[i].w;
        s2 += v[i].x * v[i].x + v[i].y * v[i].y + v[i].z * v[i].z + v[i].w * v[i].w;
    }
    s = wred_sum(s); s2 = wred_sum(s2);
    float mu = s * (1.f / DIM);
    float var = s2 * (1.f / DIM) - mu * mu;
    float rstd = rsqrtf(var + 1e-5f);
    #pragma unroll
    for (int i = 0; i < 4; i++) {
        int d = i * 128 + lane * 4;
        float4 wv = *(const float4*)(w + d);
        float4 bv = *(const float4*)(b + d);
        float o0 = (v[i].x - mu) * rstd * wv.x + bv.x;
        float o1 = (v[i].y - mu) * rstd * wv.y + bv.y;
        float o2 = (v[i].z - mu) * rstd * wv.z + bv.z;
        float o3 = (v[i].w - mu) * rstd * wv.w + bv.w;
        if (OUT == 0) {
            *(float4*)(y + (size_t)row * DIM + d) = make_float4(o0, o1, o2, o3);
        } else {
            __half2 p0, p1;
            p0.x = __float2half(o0); p0.y = __float2half(o1);
            p1.x = __float2half(o2); p1.y = __float2half(o3);
            size_t off = (size_t)row * DIM + d;
            *(__half2*)(yh + off) = p0;
            *(__half2*)(yh + off + 2) = p1;
        }
    }
}

// ---------------------------------------------------------------------------
// fp16 mma.sync GEMM: C[M,N] = A[M,K] @ B[N,K]^T (+bias, epilogue)
// BM=128, BN=128, BK=32. 128 threads = 4 warps (2x2); warp tile 64x64. 2 CTAs/SM.
// EPI: 0 bias->fp32; 1 bias+GELU->fp16; 2 bias+res->fp32; 3 bias->fp16
#define PITCHB 80
#define ARRB 10240            // 128 * 80
#define STAGEB (2 * ARRB)     // 20480 (A + B)
#define GSMEMB (2 * STAGEB)   // 40960

template <int EPI>
__global__ void __launch_bounds__(128, 2)
mma_gemm(const __half* __restrict__ A, const __half* __restrict__ B,
         const float* __restrict__ bias, const float* __restrict__ res,
         float* __restrict__ Cf, __half* __restrict__ Ch,
         int M, int N, int K) {
    extern __shared__ char smem[];
    const uint32_t sb = smem_u32(smem);
    const int tid = threadIdx.x;
    const int wid = tid >> 5, lane = tid & 31;
    const int wm = wid & 1, wn = wid >> 1;     // warp grid 2 (M) x 2 (N), tile 64x64
    const int bm = blockIdx.y * 128, bn = blockIdx.x * 128;
    const int KT = K >> 5;

    const __half* gp[2] = { A + (size_t)bm * K, B + (size_t)bn * K };

    auto load_stage = [&](int st, int k0) {
        const uint32_t sd = sb + st * STAGEB;
        #pragma unroll
        for (int i = 0; i < 8; i++) {
            int c = tid + i * 128;          // 0..1023
            int arr = c >> 9;               // 0 = A, 1 = B
            int within = c & 511;
            int row = within >> 2, seg = within & 3;
            cp16(sd + arr * ARRB + row * PITCHB + seg * 16,
                 gp[arr] + (size_t)row * K + k0 + seg * 8);
        }
        asm volatile("cp.async.commit_group;" ::: "memory");
    };

    float acc[4][8][4];
    #pragma unroll
    for (int i = 0; i < 4; i++)
        #pragma unroll
        for (int j = 0; j < 8; j++)
            #pragma unroll
            for (int f = 0; f < 4; f++) acc[i][j][f] = 0.f;

    load_stage(0, 0);

    const int arow = (lane & 15);
    const int acol = (lane >> 4) << 3;
    const int brow = (lane & 7) + ((lane >> 4) << 3);
    const int bcol = ((lane >> 3) & 1) << 3;

    for (int kt = 0; kt < KT; kt++) {
        const int st = kt & 1;
        if (kt + 1 < KT) {
            load_stage(st ^ 1, (kt + 1) << 5);
            asm volatile("cp.async.wait_group 1;" ::: "memory");
        } else {
            asm volatile("cp.async.wait_group 0;" ::: "memory");
        }
        __syncthreads();
        const uint32_t sd = sb + st * STAGEB;
        #pragma unroll
        for (int kk = 0; kk < 2; kk++) {
            uint32_t bh[8][2];
            #pragma unroll
            for (int p = 0; p < 4; p++) {
                uint32_t off = (uint32_t)(wn * 64 + p * 16 + brow) * PITCHB + (bcol + kk * 16) * 2;
                uint32_t t[4];
                ldmatrix_x4(t, sd + ARRB + off);
                bh[2 * p][0] = t[0]; bh[2 * p][1] = t[1];
                bh[2 * p + 1][0] = t[2]; bh[2 * p + 1][1] = t[3];
            }
            #pragma unroll
            for (int mt = 0; mt < 4; mt++) {
                uint32_t ah[4];
                uint32_t off = (uint32_t)(wm * 64 + mt * 16 + arow) * PITCHB + (acol + kk * 16) * 2;
                ldmatrix_x4(ah, sd + off);
                #pragma unroll
                for (int nt = 0; nt < 8; nt++)
                    mma_f16(acc[mt][nt], ah, bh[nt]);
            }
        }
        __syncthreads();
    }

    const int er = lane >> 2, ec = (lane & 3) * 2;
    #pragma unroll
    for (int mt = 0; mt < 4; mt++) {
        #pragma unroll
        for (int nt = 0; nt < 8; nt++) {
            const int n = bn + wn * 64 + nt * 8 + ec;
            const float2 bv = *(const float2*)&bias[n];
            #pragma unroll
            for (int half = 0; half < 2; half++) {
                const int m = bm + wm * 64 + mt * 16 + er + half * 8;
                float o0 = acc[mt][nt][half * 2 + 0] + bv.x;
                float o1 = acc[mt][nt][half * 2 + 1] + bv.y;
                if (EPI == 1 || EPI == 3) {
                    if (EPI == 1) {
                        o0 = 0.5f * o0 * (1.f + erff(o0 * 0.70710678118654752f));
                        o1 = 0.5f * o1 * (1.f + erff(o1 * 0.70710678118654752f));
                    }
                    __half2 hp;
                    hp.x = __float2half(o0); hp.y = __float2half(o1);
                    *(__half2*)&Ch[(size_t)m * N + n] = hp;
                } else {
                    if (EPI == 2) {
                        float2 rv = *(const float2*)&res[(size_t)m * N + n];
                        o0 += rv.x; o1 += rv.y;
                    }
                    *(float2*)&Cf[(size_t)m * N + n] = make_float2(o0, o1);
                }
            }
        }
    }
}

// ---------------------------------------------------------------------------
// Attention with fused 2D RoPE, 4 query rows per warp, fp16 qkv input.
__device__ __forceinline__ int tok_grp(int i) {
    return (i >= 21) ? 3 : (i >= 5) ? 2 : (i >= 1) ? 1 : 0;
}
#define RPW 4
#define KPAD 68
#define ATTN_SMEM ((NTOK * KPAD * 2 + 8 * RPW * 64 + 8 * RPW * 96) * 4)
#define TWO_PI 6.283185307179586f
#define NLOG10_16 -0.14391156509757025f

__global__ void attn_kernel(const __half* __restrict__ qkv,
                            const float* __restrict__ coords,
                            __half* __restrict__ oh) {
    extern __shared__ float sm[];
    float* Ks = sm;
    float* Vs = Ks + NTOK * KPAD;
    float* Qs = Vs + NTOK * KPAD;       // 8 warps * RPW * 64
    float* Ps = Qs + 8 * RPW * 64;      // 8 warps * RPW * 96
    const int b = blockIdx.x >> 3;
    const int h = blockIdx.x & 7;
    const int tid = threadIdx.x;
    const int warp = tid >> 5, lane = tid & 31;
    const int allow_tbl[4] = {9, 3, 5, 8};

    const size_t base = (size_t)b * NTOK * QKVN + h * HD;
    // Stage K,V: fp16 -> fp32 smem (8 halves per load)
    for (int i = tid; i < NTOK * 8; i += 256) {
        int n = i >> 3, c8 = (i & 7) << 3;
        ld8h_to_f(qkv + base + (size_t)n * QKVN + 512 + c8, &Ks[n * KPAD + c8]);
        ld8h_to_f(qkv + base + (size_t)n * QKVN + 1024 + c8, &Vs[n * KPAD + c8]);
    }
    __syncthreads();
    // RoPE on K in smem: tokens 1..84, j 0..15
    for (int i = tid; i < NTOK * 16; i += 256) {
        int n = i >> 4, j = i & 15;
        if (n == 0) continue;
        float freq = __expf((float)j * NLOG10_16) * TWO_PI;
        float sx, cx, sy, cy;
        sincosf(coords[(n - 1) * 2 + 0] * freq, &sx, &cx);
        sincosf(coords[(n - 1) * 2 + 1] * freq, &sy, &cy);
        float* kr = Ks + n * KPAD + j;
        float x0 = kr[0], x1 = kr[16], x2 = kr[32], x3 = kr[48];
        kr[0]  = x0 * cx - x1 * sx;
        kr[16] = x0 * sx + x1 * cx;
        kr[32] = x2 * cy - x3 * sy;
        kr[48] = x2 * sy + x3 * cy;
    }
    __syncthreads();

    float* Qw = Qs + warp * RPW * 64;
    float* Pw = Ps + warp * RPW * 96;

    for (int rb = warp * RPW; rb < NTOK; rb += 8 * RPW) {
        // Load up to RPW query rows (fp16 -> fp32 smem)
        for (int i = lane; i < RPW * 8; i += 32) {
            int rr = i >> 3, c8 = (i & 7) << 3;
            int r = rb + rr;
            if (r < NTOK)
                ld8h_to_f(qkv + base + (size_t)r * QKVN + c8, &Qw[rr * 64 + c8]);
        }
        __syncwarp();
        // RoPE on Q rows
        for (int i = lane; i < RPW * 16; i += 32) {
            int rr = i >> 4, j = i & 15;
            int r = rb + rr;
            if (r == 0 || r >= NTOK) continue;
            float freq = __expf((float)j * NLOG10_16) * TWO_PI;
            float sx, cx, sy, cy;
            sincosf(coords[(r - 1) * 2 + 0] * freq, &sx, &cx);
            sincosf(coords[(r - 1) * 2 + 1] * freq, &sy, &cy);
            float* qr = Qw + rr * 64 + j;
            float x0 = qr[0], x1 = qr[16], x2 = qr[32], x3 = qr[48];
            qr[0]  = x0 * cx - x1 * sx;
            qr[16] = x0 * sx + x1 * cx;
            qr[32] = x2 * cy - x3 * sy;
            qr[48] = x2 * sy + x3 * cy;
        }
        __syncwarp();

        int arowr[RPW];
        #pragma unroll
        for (int rr = 0; rr < RPW; rr++)
            arowr[rr] = allow_tbl[tok_grp(min(rb + rr, NTOK - 1))];

        float s[RPW][3], mxr[RPW];
        #pragma unroll
        for (int rr = 0; rr < RPW; rr++) mxr[rr] = -1e30f;

        #pragma unroll
        for (int t = 0; t < 3; t++) {
            int k = lane + t * 32;
            float acc[RPW];
            #pragma unroll
            for (int rr = 0; rr < RPW; rr++) acc[rr] = 0.f;
            if (k < NTOK) {
                #pragma unroll
                for (int d4 = 0; d4 < 16; d4++) {
                    float4 kk = *(float4*)&Ks[k * KPAD + d4 * 4];
                    #pragma unroll
                    for (int rr = 0; rr < RPW; rr++) {
                        float4 q = *(float4*)&Qw[rr * 64 + d4 * 4];
                        acc[rr] += q.x * kk.x + q.y * kk.y + q.z * kk.z + q.w * kk.w;
                    }
                }
            }
            #pragma unroll
            for (int rr = 0; rr < RPW; rr++) {
                bool allow = (k < NTOK) && ((arowr[rr] >> tok_grp(k < NTOK ? k : 0)) & 1);
                float v = allow ? acc[rr] * 0.125f : -1e30f;
                s[rr][t] = v;
                mxr[rr] = fmaxf(mxr[rr], v);
            }
        }
        float invr[RPW];
        #pragma unroll
        for (int rr = 0; rr < RPW; rr++) mxr[rr] = wred_max(mxr[rr]);
        float sumr[RPW];
        #pragma unroll
        for (int rr = 0; rr < RPW; rr++) sumr[rr] = 0.f;
        #pragma unroll
        for (int t = 0; t < 3; t++) {
            int k = lane + t * 32;
            if (k < NTOK) {
                #pragma unroll
                for (int rr = 0; rr < RPW; rr++) {
                    float p = __expf(s[rr][t] - mxr[rr]);
                    sumr[rr] += p;
                    Pw[rr * 96 + k] = p;
                }
            }
        }
        #pragma unroll
        for (int rr = 0; rr < RPW; rr++) invr[rr] = 1.f / wred_sum(sumr[rr]);
        __syncwarp();

        #pragma unroll
        for (int t = 0; t < 2; t++) {
            int d = lane + t * 32;
            float o[RPW];
            #pragma unroll
            for (int rr = 0; rr < RPW; rr++) o[rr] = 0.f;
            #pragma unroll 4
            for (int k4 = 0; k4 < 21; k4++) {
                #pragma unroll
                for (int kq = 0; kq < 4; kq++) {
                    int k = k4 * 4 + kq;
                    float vv = Vs[k * KPAD + d];
                    #pragma unroll
                    for (int rr = 0; rr < RPW; rr++)
                        o[rr] += Pw[rr * 96 + k] * vv;
                }
            }
            {
                float vv = Vs[84 * KPAD + d];
                #pragma unroll
                for (int rr = 0; rr < RPW; rr++)
                    o[rr] += Pw[rr * 96 + 84] * vv;
            }
            #pragma unroll
            for (int rr = 0; rr < RPW; rr++) {
                int r = rb + rr;
                if (r < NTOK)
                    oh[((size_t)b * NTOK + r) * DIM + h * HD + d] =
                        __float2half(o[rr] * invr[rr]);
            }
        }
        __syncwarp();
    }
}

// ---------------------------------------------------------------------------
extern "C" void kernel_launch(void* const* d_in, const int* in_sizes, int n_in,
                              void* d_out, int out_size) {
    const float* x      = (const float*)d_in[0];
    const float* coords = (const float*)d_in[1];
    const float* ln1_w  = (const float*)d_in[2];
    const float* ln1_b  = (const float*)d_in[3];
    const float* qkv_w  = (const float*)d_in[4];
    const float* qkv_b  = (const float*)d_in[5];
    const float* proj_w = (const float*)d_in[6];
    const float* proj_b = (const float*)d_in[7];
    const float* ln2_w  = (const float*)d_in[8];
    const float* ln2_b  = (const float*)d_in[9];
    const float* fc1_w  = (const float*)d_in[10];
    const float* fc1_b  = (const float*)d_in[11];
    const float* fc2_w  = (const float*)d_in[12];
    const float* fc2_b  = (const float*)d_in[13];
    const float* lnf_w  = (const float*)d_in[14];
    const float* lnf_b  = (const float*)d_in[15];
    float* out = (float*)d_out;

    float *gx;
    __half *gqkvh, *a5, *a2, *wh;
    cudaGetSymbolAddress((void**)&gx, g_x);
    cudaGetSymbolAddress((void**)&gqkvh, g_qkvh);
    cudaGetSymbolAddress((void**)&a5, g_a512);
    cudaGetSymbolAddress((void**)&a2, g_a2048);
    cudaGetSymbolAddress((void**)&wh, g_wh);

    static int attr_set = 0;
    if (!attr_set) {
        cudaFuncSetAttribute(attn_kernel, cudaFuncAttributeMaxDynamicSharedMemorySize, ATTN_SMEM);
        cudaFuncSetAttribute(mma_gemm<0>, cudaFuncAttributeMaxDynamicSharedMemorySize, GSMEMB);
        cudaFuncSetAttribute(mma_gemm<1>, cudaFuncAttributeMaxDynamicSharedMemorySize, GSMEMB);
        cudaFuncSetAttribute(mma_gemm<2>, cudaFuncAttributeMaxDynamicSharedMemorySize, GSMEMB);
        cudaFuncSetAttribute(mma_gemm<3>, cudaFuncAttributeMaxDynamicSharedMemorySize, GSMEMB);
        attr_set = 1;
    }

    // Weight prep: transpose + fp16 convert
    for (int l = 0; l < 6; l++) {
        prep_w<<<dim3(QKVN / 32, DIM / 32), dim3(32, 8)>>>(
            qkv_w + (size_t)l * DIM * QKVN, wh + (size_t)l * LOFF + OFF_QKV, DIM, QKVN);
        prep_w<<<dim3(DIM / 32, DIM / 32), dim3(32, 8)>>>(
            proj_w + (size_t)l * DIM * DIM, wh + (size_t)l * LOFF + OFF_PROJ, DIM, DIM);
        prep_w<<<dim3(FFN / 32, DIM / 32), dim3(32, 8)>>>(
            fc1_w + (size_t)l * DIM * FFN, wh + (size_t)l * LOFF + OFF_FC1, DIM, FFN);
        prep_w<<<dim3(DIM / 32, FFN / 32), dim3(32, 8)>>>(
            fc2_w + (size_t)l * FFN * DIM, wh + (size_t)l * LOFF + OFF_FC2, FFN, DIM);
    }

    cudaMemcpyAsync(gx, x, (size_t)M_ROWS * DIM * sizeof(float), cudaMemcpyDeviceToDevice, 0);

    const int ln_grid = (M_ROWS + 7) / 8;

    for (int l = 0; l < 6; l++) {
        const __half* qkvT = wh + (size_t)l * LOFF + OFF_QKV;
        const __half* projT = wh + (size_t)l * LOFF + OFF_PROJ;
        const __half* fc1T = wh + (size_t)l * LOFF + OFF_FC1;
        const __half* fc2T = wh + (size_t)l * LOFF + OFF_FC2;

        // LN1 -> fp16
        ln_kernel<1><<<ln_grid, 256>>>(gx, ln1_w + l * DIM, ln1_b + l * DIM, nullptr, a5);
        // QKV GEMM -> fp16 qkv (unroped; rope fused into attention)
        mma_gemm<3><<<dim3(QKVN / 128, M_ROWS / 128), 128, GSMEMB>>>(
            a5, qkvT, qkv_b + (size_t)l * QKVN, nullptr,
            nullptr, gqkvh, M_ROWS, QKVN, DIM);
        // Attention (fused RoPE) -> fp16
        attn_kernel<<<BATCH * HEADS, 256, ATTN_SMEM>>>(gqkvh, coords, a5);
        // proj GEMM + residual -> g_x
        mma_gemm<2><<<dim3(DIM / 128, M_ROWS / 128), 128, GSMEMB>>>(
            a5, projT, proj_b + (size_t)l * DIM, gx,
            gx, nullptr, M_ROWS, DIM, DIM);
        // LN2 -> fp16
        ln_kernel<1><<<ln_grid, 256>>>(gx, ln2_w + l * DIM, ln2_b + l * DIM, nullptr, a5);
        // fc1 + GELU -> fp16
        mma_gemm<1><<<dim3(FFN / 128, M_ROWS / 128), 128, GSMEMB>>>(
            a5, fc1T, fc1_b + (size_t)l * FFN, nullptr,
            nullptr, a2, M_ROWS, FFN, DIM);
        // fc2 + residual -> g_x
        mma_gemm<2><<<dim3(DIM / 128, M_ROWS / 128), 128, GSMEMB>>>(
            a2, fc2T, fc2_b + (size_t)l * DIM, gx,
            gx, nullptr, M_ROWS, DIM, FFN);
    }
    // Final LN -> out (fp32)
    ln_kernel<0><<<ln_grid, 256>>>(gx, lnf_w, lnf_b, out, nullptr);
}